// round 1
// baseline (speedup 1.0000x reference)
#include <cuda_runtime.h>
#include <math.h>

#define T_STEPS 100
#define B_SZ 4096
#define A_SZ 32
#define H_SZ 1024
#define S_SZ 256

// ---------------- scratch (static device globals; no allocation) ----------------
__device__ float g_x [B_SZ * A_SZ];          // current sample x  [4096,32]
__device__ float g_h1[B_SZ * H_SZ];          // activations ping  [4096,1024]
__device__ float g_h2[B_SZ * H_SZ];          // activations pong  [4096,1024]
__device__ float g_cs[B_SZ * H_SZ];          // state @ W1_state + b1 (step-invariant)
__device__ float g_tv[T_STEPS * H_SZ];       // temb_i @ W1_temb  (per-step [1024] vec)
__device__ float g_sr [T_STEPS];             // sqrt(1/alpha_bar)
__device__ float g_srm[T_STEPS];             // sqrt(1/alpha_bar - 1)
__device__ float g_p1 [T_STEPS];             // posterior mean coef 1
__device__ float g_p2 [T_STEPS];             // posterior mean coef 2
__device__ float g_sig[T_STEPS];             // exp(0.5*log_var) = sqrt(clipped post_var)

__device__ __forceinline__ float mishf(float v) {
    // softplus: log1p(exp(v)) — for v>20 softplus(v)==v to fp32 precision
    float sp = (v > 20.0f) ? v : log1pf(expf(v));
    return v * tanhf(sp);
}

// ---------------- schedule precompute (serial, trivial) ----------------
__global__ void sched_kernel() {
    if (threadIdx.x != 0) return;
    float ab = 1.0f;
    for (int i = 0; i < T_STEPS; i++) {
        float beta  = 1e-4f + (0.2f - 1e-4f) * ((float)i / 99.0f);
        float alpha = 1.0f - beta;
        float abprev = ab;            // alpha_bar_prev[i]
        ab *= alpha;                  // alpha_bar[i]
        float one_m_ab = 1.0f - ab;
        float post_var = beta * (1.0f - abprev) / one_m_ab;
        g_sr [i] = sqrtf(1.0f / ab);
        g_srm[i] = sqrtf(1.0f / ab - 1.0f);
        g_p1 [i] = beta * sqrtf(abprev) / one_m_ab;
        g_p2 [i] = (1.0f - abprev) * sqrtf(alpha) / one_m_ab;
        g_sig[i] = sqrtf(fmaxf(post_var, 1e-20f));
    }
}

// ---------------- per-step time-embedding vector precompute ----------------
// One block per timestep i. Produces g_tv[i] = (MLP_t(sinpos(i))) @ W1[32:48,:]
__global__ void temb_kernel(const float* __restrict__ w_t1, const float* __restrict__ b_t1,
                            const float* __restrict__ w_t2, const float* __restrict__ b_t2,
                            const float* __restrict__ w1t /* = w1 + 32*1024 */) {
    int i = blockIdx.x;
    int t = threadIdx.x;  // 256 threads
    __shared__ float emb[16];
    __shared__ float e1[256];
    __shared__ float temb[16];

    if (t < 8) {
        float freq = expf((float)t * (-logf(10000.0f) / 7.0f));
        float ang  = (float)i * freq;
        emb[t]     = sinf(ang);
        emb[t + 8] = cosf(ang);
    }
    __syncthreads();
    {
        float s = b_t1[t];
        #pragma unroll
        for (int j = 0; j < 16; j++) s += emb[j] * w_t1[j * 256 + t];
        e1[t] = mishf(s);
    }
    __syncthreads();
    if (t < 16) {
        float s = b_t2[t];
        for (int p = 0; p < 256; p++) s += e1[p] * w_t2[p * 16 + t];
        temb[t] = s;
    }
    __syncthreads();
    for (int n = t; n < H_SZ; n += 256) {
        float s = 0.0f;
        #pragma unroll
        for (int q = 0; q < 16; q++) s += temb[q] * w1t[q * H_SZ + n];
        g_tv[i * H_SZ + n] = s;
    }
}

// ---------------- x init copy / final clip ----------------
__global__ void copy_x_kernel(const float* __restrict__ x_init) {
    int idx = blockIdx.x * blockDim.x + threadIdx.x;
    g_x[idx] = x_init[idx];
}
__global__ void clip_out_kernel(float* __restrict__ out) {
    int idx = blockIdx.x * blockDim.x + threadIdx.x;
    out[idx] = fminf(fmaxf(g_x[idx], -1.0f), 1.0f);
}

// ---------------- 128x128x8 register-blocked SGEMM with fused epilogue ----------------
// C[M,N] = epi( A[M,K] @ B[K,N] )
// EPI 0: acc + bias[n]                      (C_state precompute)
// EPI 1: mish(acc + bias[n])                (layers 2,3)
// EPI 2: mish(acc + bias[n] + add[m,n])     (layer 1: bias=g_tv[i], add=g_cs)
// Requires M%128==0, N%128==0, K%8==0, K%4==0 alignment for float4.
template <int EPI>
__global__ __launch_bounds__(256)
void sgemm128(const float* __restrict__ A, const float* __restrict__ Bm,
              const float* __restrict__ bias, const float* __restrict__ add,
              float* __restrict__ C, int M, int N, int K) {
    const int BM = 128, BN = 128, BK = 8;
    __shared__ float As[BK][BM];
    __shared__ float Bs[BK][BN];

    int tid  = threadIdx.x;
    int brow = blockIdx.y, bcol = blockIdx.x;
    A  += (size_t)brow * BM * K;
    Bm += (size_t)bcol * BN;
    C  += (size_t)brow * BM * N + (size_t)bcol * BN;
    const float* biasp = bias + (size_t)bcol * BN;
    const float* addp  = (EPI == 2) ? add + (size_t)brow * BM * N + (size_t)bcol * BN : nullptr;

    int aRow = tid >> 1;          // 0..127
    int aCol = (tid & 1) * 4;     // 0 or 4
    int bRow = tid >> 5;          // 0..7
    int bCol = (tid & 31) * 4;    // 0..124
    int tx = tid & 15, ty = tid >> 4;

    float acc[8][8];
    #pragma unroll
    for (int i = 0; i < 8; i++)
        #pragma unroll
        for (int j = 0; j < 8; j++) acc[i][j] = 0.0f;

    for (int kk = 0; kk < K; kk += BK) {
        float4 a = *reinterpret_cast<const float4*>(A + (size_t)aRow * K + kk + aCol);
        As[aCol + 0][aRow] = a.x;
        As[aCol + 1][aRow] = a.y;
        As[aCol + 2][aRow] = a.z;
        As[aCol + 3][aRow] = a.w;
        *reinterpret_cast<float4*>(&Bs[bRow][bCol]) =
            *reinterpret_cast<const float4*>(Bm + (size_t)(kk + bRow) * N + bCol);
        __syncthreads();

        #pragma unroll
        for (int k = 0; k < BK; k++) {
            float ar[8], br[8];
            #pragma unroll
            for (int i = 0; i < 8; i++) ar[i] = As[k][ty * 8 + i];
            #pragma unroll
            for (int j = 0; j < 8; j++) br[j] = Bs[k][tx * 8 + j];
            #pragma unroll
            for (int i = 0; i < 8; i++)
                #pragma unroll
                for (int j = 0; j < 8; j++)
                    acc[i][j] = fmaf(ar[i], br[j], acc[i][j]);
        }
        __syncthreads();
    }

    #pragma unroll
    for (int i = 0; i < 8; i++) {
        int m = ty * 8 + i;
        #pragma unroll
        for (int j = 0; j < 8; j += 4) {
            int n = tx * 8 + j;
            float4 v;
            float* vv = &v.x;
            #pragma unroll
            for (int q = 0; q < 4; q++) {
                float s = acc[i][j + q] + biasp[n + q];
                if (EPI == 2) s += addp[(size_t)m * N + n + q];
                if (EPI >= 1) s = mishf(s);
                vv[q] = s;
            }
            *reinterpret_cast<float4*>(C + (size_t)m * N + n) = v;
        }
    }
}

// ---------------- fused final-layer GEMM (N=32) + diffusion update ----------------
// eps = g_h1 @ Wf + bf ;  x = p1*clip(sr*x - srm*eps) + p2*x + (i!=0)*sig*z
__global__ __launch_bounds__(256)
void update_kernel(const float* __restrict__ wf, const float* __restrict__ bf,
                   const float* __restrict__ noise, int step) {
    __shared__ float As[32][32];
    __shared__ float Bs[32][32];
    int tid = threadIdx.x;
    int bm  = blockIdx.x * 32;
    int tx = tid & 31, ty = tid >> 5;   // ty 0..7
    int lr = tid >> 3;                  // 0..31 (load row)
    int lc = (tid & 7) * 4;             // 0,4,...,28 (load col base)

    float acc[4] = {0.f, 0.f, 0.f, 0.f};
    for (int kk = 0; kk < H_SZ; kk += 32) {
        *reinterpret_cast<float4*>(&As[lr][lc]) =
            *reinterpret_cast<const float4*>(&g_h1[(size_t)(bm + lr) * H_SZ + kk + lc]);
        *reinterpret_cast<float4*>(&Bs[lr][lc]) =
            *reinterpret_cast<const float4*>(wf + (size_t)(kk + lr) * 32 + lc);
        __syncthreads();
        #pragma unroll
        for (int k = 0; k < 32; k++) {
            float b = Bs[k][tx];
            #pragma unroll
            for (int r = 0; r < 4; r++)
                acc[r] = fmaf(As[ty * 4 + r][k], b, acc[r]);
        }
        __syncthreads();
    }

    float sr  = g_sr[step], srm = g_srm[step];
    float p1  = g_p1[step], p2  = g_p2[step];
    float sig = (step != 0) ? g_sig[step] : 0.0f;
    const float* z = noise + (size_t)(T_STEPS - 1 - step) * B_SZ * A_SZ;

    #pragma unroll
    for (int r = 0; r < 4; r++) {
        int m = bm + ty * 4 + r;
        float eps = acc[r] + bf[tx];
        float xo  = g_x[(size_t)m * A_SZ + tx];
        float xr  = fminf(fmaxf(sr * xo - srm * eps, -1.0f), 1.0f);
        float xn  = p1 * xr + p2 * xo + sig * z[(size_t)m * A_SZ + tx];
        g_x[(size_t)m * A_SZ + tx] = xn;
    }
}

// ---------------- launch ----------------
extern "C" void kernel_launch(void* const* d_in, const int* in_sizes, int n_in,
                              void* d_out, int out_size) {
    const float* state  = (const float*)d_in[0];
    const float* w_t1   = (const float*)d_in[1];
    const float* b_t1   = (const float*)d_in[2];
    const float* w_t2   = (const float*)d_in[3];
    const float* b_t2   = (const float*)d_in[4];
    const float* w1     = (const float*)d_in[5];
    const float* b1     = (const float*)d_in[6];
    const float* w2     = (const float*)d_in[7];
    const float* b2     = (const float*)d_in[8];
    const float* w3     = (const float*)d_in[9];
    const float* b3     = (const float*)d_in[10];
    const float* wf     = (const float*)d_in[11];
    const float* bf     = (const float*)d_in[12];
    const float* x_init = (const float*)d_in[13];
    const float* noise  = (const float*)d_in[14];

    float *p_x, *p_h1, *p_h2, *p_cs, *p_tv;
    cudaGetSymbolAddress((void**)&p_x,  g_x);
    cudaGetSymbolAddress((void**)&p_h1, g_h1);
    cudaGetSymbolAddress((void**)&p_h2, g_h2);
    cudaGetSymbolAddress((void**)&p_cs, g_cs);
    cudaGetSymbolAddress((void**)&p_tv, g_tv);

    sched_kernel<<<1, 32>>>();
    temb_kernel<<<T_STEPS, 256>>>(w_t1, b_t1, w_t2, b_t2, w1 + 32 * H_SZ);
    copy_x_kernel<<<(B_SZ * A_SZ) / 256, 256>>>(x_init);

    dim3 g1(H_SZ / 128, B_SZ / 128);  // (8, 32)
    // C_state = state @ W1[48:304,:] + b1  (once)
    sgemm128<0><<<g1, 256>>>(state, w1 + 48 * H_SZ, b1, nullptr, p_cs, B_SZ, H_SZ, S_SZ);

    for (int i = T_STEPS - 1; i >= 0; --i) {
        // h1 = mish(x @ W1[0:32,:] + g_cs + g_tv[i])
        sgemm128<2><<<g1, 256>>>(p_x, w1, p_tv + i * H_SZ, p_cs, p_h1, B_SZ, H_SZ, A_SZ);
        // h2 = mish(h1 @ W2 + b2)
        sgemm128<1><<<g1, 256>>>(p_h1, w2, b2, nullptr, p_h2, B_SZ, H_SZ, H_SZ);
        // h3 = mish(h2 @ W3 + b3)  (reuse h1 buffer)
        sgemm128<1><<<g1, 256>>>(p_h2, w3, b3, nullptr, p_h1, B_SZ, H_SZ, H_SZ);
        // eps + diffusion update (fused)
        update_kernel<<<B_SZ / 32, 256>>>(wf, bf, noise, i);
    }
    clip_out_kernel<<<(B_SZ * A_SZ) / 256, 256>>>((float*)d_out);
}

// round 2
// speedup vs baseline: 2.3199x; 2.3199x over previous
#include <cuda_runtime.h>
#include <math.h>
#include <stdint.h>

#define T_STEPS 100
#define B_SZ 4096
#define A_SZ 32
#define H_SZ 1024
#define S_SZ 256

// ---------------- scratch (static device globals; no allocation) ----------------
__device__ float g_x [B_SZ * A_SZ];
__device__ float g_h1[B_SZ * H_SZ];
__device__ float g_h2[B_SZ * H_SZ];
__device__ float g_cs[B_SZ * H_SZ];
__device__ float g_tv[T_STEPS * H_SZ];
__device__ float g_sr [T_STEPS];
__device__ float g_srm[T_STEPS];
__device__ float g_p1 [T_STEPS];
__device__ float g_p2 [T_STEPS];
__device__ float g_sig[T_STEPS];

__device__ __forceinline__ float mishf(float v) {
    float sp = (v > 20.0f) ? v : log1pf(expf(v));
    return v * tanhf(sp);
}

__device__ __forceinline__ uint32_t f2tf32(float f) {
    uint32_t u;
    asm("cvt.rna.tf32.f32 %0, %1;" : "=r"(u) : "f"(f));
    return u;
}

// ---------------- schedule precompute ----------------
__global__ void sched_kernel() {
    if (threadIdx.x != 0) return;
    float ab = 1.0f;
    for (int i = 0; i < T_STEPS; i++) {
        float beta  = 1e-4f + (0.2f - 1e-4f) * ((float)i / 99.0f);
        float alpha = 1.0f - beta;
        float abprev = ab;
        ab *= alpha;
        float one_m_ab = 1.0f - ab;
        float post_var = beta * (1.0f - abprev) / one_m_ab;
        g_sr [i] = sqrtf(1.0f / ab);
        g_srm[i] = sqrtf(1.0f / ab - 1.0f);
        g_p1 [i] = beta * sqrtf(abprev) / one_m_ab;
        g_p2 [i] = (1.0f - abprev) * sqrtf(alpha) / one_m_ab;
        g_sig[i] = sqrtf(fmaxf(post_var, 1e-20f));
    }
}

// ---------------- per-step time-embedding vector precompute ----------------
__global__ void temb_kernel(const float* __restrict__ w_t1, const float* __restrict__ b_t1,
                            const float* __restrict__ w_t2, const float* __restrict__ b_t2,
                            const float* __restrict__ w1t) {
    int i = blockIdx.x;
    int t = threadIdx.x;
    __shared__ float emb[16];
    __shared__ float e1[256];
    __shared__ float temb[16];

    if (t < 8) {
        float freq = expf((float)t * (-logf(10000.0f) / 7.0f));
        float ang  = (float)i * freq;
        emb[t]     = sinf(ang);
        emb[t + 8] = cosf(ang);
    }
    __syncthreads();
    {
        float s = b_t1[t];
        #pragma unroll
        for (int j = 0; j < 16; j++) s += emb[j] * w_t1[j * 256 + t];
        e1[t] = mishf(s);
    }
    __syncthreads();
    if (t < 16) {
        float s = b_t2[t];
        for (int p = 0; p < 256; p++) s += e1[p] * w_t2[p * 16 + t];
        temb[t] = s;
    }
    __syncthreads();
    for (int n = t; n < H_SZ; n += 256) {
        float s = 0.0f;
        #pragma unroll
        for (int q = 0; q < 16; q++) s += temb[q] * w1t[q * H_SZ + n];
        g_tv[i * H_SZ + n] = s;
    }
}

__global__ void copy_x_kernel(const float* __restrict__ x_init) {
    int idx = blockIdx.x * blockDim.x + threadIdx.x;
    g_x[idx] = x_init[idx];
}
__global__ void clip_out_kernel(float* __restrict__ out) {
    int idx = blockIdx.x * blockDim.x + threadIdx.x;
    out[idx] = fminf(fmaxf(g_x[idx], -1.0f), 1.0f);
}

// ---------------- tf32 tensor-core GEMM, 128x128 tile, BK=16, double-buffered ----------------
// C[M,N] = epi( A[M,K] @ B[K,N] )
// EPI 0: acc + bias[n]
// EPI 1: mish(acc + bias[n])
// EPI 2: mish(acc + bias[n] + add[m,n])
// Requires M%128==0, N%128==0, K%16==0.
#define TBM 128
#define TBN 128
#define TBK 16
#define AS_STRIDE 20   // pad: 16 + 4 -> conflict-free frag loads (bank = (20m+k)%32)
#define BS_STRIDE 136  // pad: 128 + 8 -> conflict-free frag loads (bank = (136k+n)%32)

template <int EPI>
__global__ __launch_bounds__(256)
void tf32gemm(const float* __restrict__ A, const float* __restrict__ Bm,
              const float* __restrict__ bias, const float* __restrict__ add,
              float* __restrict__ C, int M, int N, int K) {
    __shared__ float As[2][TBM][AS_STRIDE];
    __shared__ float Bs[2][TBK][BS_STRIDE];

    const int tid  = threadIdx.x;
    const int lane = tid & 31;
    const int warp = tid >> 5;
    const int warpM = (warp >> 2) * 64;   // 0 or 64
    const int warpN = (warp & 3) * 32;    // 0,32,64,96
    const int groupID = lane >> 2;        // 0..7
    const int tid4    = lane & 3;         // 0..3

    const int m0 = blockIdx.y * TBM;
    const int n0 = blockIdx.x * TBN;

    // global load mapping (2 float4 each side per thread)
    const int aM0 = tid >> 2;              // 0..63
    const int aK0 = (tid & 3) * 4;         // 0,4,8,12
    const int aM1 = aM0 + 64;
    const int bK0 = tid >> 5;              // 0..7
    const int bN0 = (tid & 31) * 4;        // 0..124
    const int bK1 = bK0 + 8;

    const float* Ap = A + (size_t)m0 * K;
    const float* Bp = Bm + n0;

    float4 ra0, ra1, rb0, rb1;

    // prologue: tile 0
    ra0 = *reinterpret_cast<const float4*>(Ap + (size_t)aM0 * K + aK0);
    ra1 = *reinterpret_cast<const float4*>(Ap + (size_t)aM1 * K + aK0);
    rb0 = *reinterpret_cast<const float4*>(Bp + (size_t)bK0 * N + bN0);
    rb1 = *reinterpret_cast<const float4*>(Bp + (size_t)bK1 * N + bN0);

    float acc[4][4][4];
    #pragma unroll
    for (int i = 0; i < 4; i++)
        #pragma unroll
        for (int j = 0; j < 4; j++)
            #pragma unroll
            for (int q = 0; q < 4; q++) acc[i][j][q] = 0.0f;

    const int nIter = K / TBK;

    // store tile 0 into buf 0 (tf32-round)
    {
        float4 t;
        t.x = __uint_as_float(f2tf32(ra0.x)); t.y = __uint_as_float(f2tf32(ra0.y));
        t.z = __uint_as_float(f2tf32(ra0.z)); t.w = __uint_as_float(f2tf32(ra0.w));
        *reinterpret_cast<float4*>(&As[0][aM0][aK0]) = t;
        t.x = __uint_as_float(f2tf32(ra1.x)); t.y = __uint_as_float(f2tf32(ra1.y));
        t.z = __uint_as_float(f2tf32(ra1.z)); t.w = __uint_as_float(f2tf32(ra1.w));
        *reinterpret_cast<float4*>(&As[0][aM1][aK0]) = t;
        t.x = __uint_as_float(f2tf32(rb0.x)); t.y = __uint_as_float(f2tf32(rb0.y));
        t.z = __uint_as_float(f2tf32(rb0.z)); t.w = __uint_as_float(f2tf32(rb0.w));
        *reinterpret_cast<float4*>(&Bs[0][bK0][bN0]) = t;
        t.x = __uint_as_float(f2tf32(rb1.x)); t.y = __uint_as_float(f2tf32(rb1.y));
        t.z = __uint_as_float(f2tf32(rb1.z)); t.w = __uint_as_float(f2tf32(rb1.w));
        *reinterpret_cast<float4*>(&Bs[0][bK1][bN0]) = t;
    }
    __syncthreads();

    int buf = 0;
    for (int it = 0; it < nIter; ++it) {
        // prefetch next tile into registers
        if (it + 1 < nIter) {
            int kk = (it + 1) * TBK;
            ra0 = *reinterpret_cast<const float4*>(Ap + (size_t)aM0 * K + kk + aK0);
            ra1 = *reinterpret_cast<const float4*>(Ap + (size_t)aM1 * K + kk + aK0);
            rb0 = *reinterpret_cast<const float4*>(Bp + (size_t)(kk + bK0) * N + bN0);
            rb1 = *reinterpret_cast<const float4*>(Bp + (size_t)(kk + bK1) * N + bN0);
        }

        // compute: 2 k-steps of 8
        #pragma unroll
        for (int ks = 0; ks < 2; ks++) {
            const int kB = ks * 8;
            uint32_t af[4][4], bfr[4][2];
            #pragma unroll
            for (int mi = 0; mi < 4; mi++) {
                int m = warpM + mi * 16 + groupID;
                af[mi][0] = __float_as_uint(As[buf][m    ][kB + tid4]);
                af[mi][1] = __float_as_uint(As[buf][m + 8][kB + tid4]);
                af[mi][2] = __float_as_uint(As[buf][m    ][kB + tid4 + 4]);
                af[mi][3] = __float_as_uint(As[buf][m + 8][kB + tid4 + 4]);
            }
            #pragma unroll
            for (int ni = 0; ni < 4; ni++) {
                int n = warpN + ni * 8 + groupID;
                bfr[ni][0] = __float_as_uint(Bs[buf][kB + tid4    ][n]);
                bfr[ni][1] = __float_as_uint(Bs[buf][kB + tid4 + 4][n]);
            }
            #pragma unroll
            for (int mi = 0; mi < 4; mi++)
                #pragma unroll
                for (int ni = 0; ni < 4; ni++) {
                    asm volatile(
                        "mma.sync.aligned.m16n8k8.row.col.f32.tf32.tf32.f32 "
                        "{%0,%1,%2,%3}, {%4,%5,%6,%7}, {%8,%9}, {%0,%1,%2,%3};"
                        : "+f"(acc[mi][ni][0]), "+f"(acc[mi][ni][1]),
                          "+f"(acc[mi][ni][2]), "+f"(acc[mi][ni][3])
                        : "r"(af[mi][0]), "r"(af[mi][1]), "r"(af[mi][2]), "r"(af[mi][3]),
                          "r"(bfr[ni][0]), "r"(bfr[ni][1]));
                }
        }

        // stage next tile into the other buffer
        if (it + 1 < nIter) {
            int nb = buf ^ 1;
            float4 t;
            t.x = __uint_as_float(f2tf32(ra0.x)); t.y = __uint_as_float(f2tf32(ra0.y));
            t.z = __uint_as_float(f2tf32(ra0.z)); t.w = __uint_as_float(f2tf32(ra0.w));
            *reinterpret_cast<float4*>(&As[nb][aM0][aK0]) = t;
            t.x = __uint_as_float(f2tf32(ra1.x)); t.y = __uint_as_float(f2tf32(ra1.y));
            t.z = __uint_as_float(f2tf32(ra1.z)); t.w = __uint_as_float(f2tf32(ra1.w));
            *reinterpret_cast<float4*>(&As[nb][aM1][aK0]) = t;
            t.x = __uint_as_float(f2tf32(rb0.x)); t.y = __uint_as_float(f2tf32(rb0.y));
            t.z = __uint_as_float(f2tf32(rb0.z)); t.w = __uint_as_float(f2tf32(rb0.w));
            *reinterpret_cast<float4*>(&Bs[nb][bK0][bN0]) = t;
            t.x = __uint_as_float(f2tf32(rb1.x)); t.y = __uint_as_float(f2tf32(rb1.y));
            t.z = __uint_as_float(f2tf32(rb1.z)); t.w = __uint_as_float(f2tf32(rb1.w));
            *reinterpret_cast<float4*>(&Bs[nb][bK1][bN0]) = t;
            __syncthreads();
            buf = nb;
        }
    }

    // epilogue
    #pragma unroll
    for (int mi = 0; mi < 4; mi++) {
        int row0 = m0 + warpM + mi * 16 + groupID;
        int row1 = row0 + 8;
        #pragma unroll
        for (int ni = 0; ni < 4; ni++) {
            int col = n0 + warpN + ni * 8 + tid4 * 2;
            float b0v = bias[col], b1v = bias[col + 1];
            float s0 = acc[mi][ni][0] + b0v;
            float s1 = acc[mi][ni][1] + b1v;
            float s2 = acc[mi][ni][2] + b0v;
            float s3 = acc[mi][ni][3] + b1v;
            if (EPI == 2) {
                s0 += add[(size_t)row0 * N + col];
                s1 += add[(size_t)row0 * N + col + 1];
                s2 += add[(size_t)row1 * N + col];
                s3 += add[(size_t)row1 * N + col + 1];
            }
            if (EPI >= 1) {
                s0 = mishf(s0); s1 = mishf(s1); s2 = mishf(s2); s3 = mishf(s3);
            }
            float2 v0 = make_float2(s0, s1);
            float2 v1 = make_float2(s2, s3);
            *reinterpret_cast<float2*>(C + (size_t)row0 * N + col) = v0;
            *reinterpret_cast<float2*>(C + (size_t)row1 * N + col) = v1;
        }
    }
}

// ---------------- fused final-layer GEMM (N=32) + diffusion update ----------------
__global__ __launch_bounds__(256)
void update_kernel(const float* __restrict__ wf, const float* __restrict__ bf,
                   const float* __restrict__ noise, int step) {
    __shared__ float As[32][32];
    __shared__ float Bs[32][32];
    int tid = threadIdx.x;
    int bm  = blockIdx.x * 32;
    int tx = tid & 31, ty = tid >> 5;
    int lr = tid >> 3;
    int lc = (tid & 7) * 4;

    float acc[4] = {0.f, 0.f, 0.f, 0.f};
    for (int kk = 0; kk < H_SZ; kk += 32) {
        *reinterpret_cast<float4*>(&As[lr][lc]) =
            *reinterpret_cast<const float4*>(&g_h1[(size_t)(bm + lr) * H_SZ + kk + lc]);
        *reinterpret_cast<float4*>(&Bs[lr][lc]) =
            *reinterpret_cast<const float4*>(wf + (size_t)(kk + lr) * 32 + lc);
        __syncthreads();
        #pragma unroll
        for (int k = 0; k < 32; k++) {
            float b = Bs[k][tx];
            #pragma unroll
            for (int r = 0; r < 4; r++)
                acc[r] = fmaf(As[ty * 4 + r][k], b, acc[r]);
        }
        __syncthreads();
    }

    float sr  = g_sr[step], srm = g_srm[step];
    float p1  = g_p1[step], p2  = g_p2[step];
    float sig = (step != 0) ? g_sig[step] : 0.0f;
    const float* z = noise + (size_t)(T_STEPS - 1 - step) * B_SZ * A_SZ;

    #pragma unroll
    for (int r = 0; r < 4; r++) {
        int m = bm + ty * 4 + r;
        float eps = acc[r] + bf[tx];
        float xo  = g_x[(size_t)m * A_SZ + tx];
        float xr  = fminf(fmaxf(sr * xo - srm * eps, -1.0f), 1.0f);
        float xn  = p1 * xr + p2 * xo + sig * z[(size_t)m * A_SZ + tx];
        g_x[(size_t)m * A_SZ + tx] = xn;
    }
}

// ---------------- launch ----------------
extern "C" void kernel_launch(void* const* d_in, const int* in_sizes, int n_in,
                              void* d_out, int out_size) {
    const float* state  = (const float*)d_in[0];
    const float* w_t1   = (const float*)d_in[1];
    const float* b_t1   = (const float*)d_in[2];
    const float* w_t2   = (const float*)d_in[3];
    const float* b_t2   = (const float*)d_in[4];
    const float* w1     = (const float*)d_in[5];
    const float* b1     = (const float*)d_in[6];
    const float* w2     = (const float*)d_in[7];
    const float* b2     = (const float*)d_in[8];
    const float* w3     = (const float*)d_in[9];
    const float* b3     = (const float*)d_in[10];
    const float* wf     = (const float*)d_in[11];
    const float* bf     = (const float*)d_in[12];
    const float* x_init = (const float*)d_in[13];
    const float* noise  = (const float*)d_in[14];

    float *p_x, *p_h1, *p_h2, *p_cs, *p_tv;
    cudaGetSymbolAddress((void**)&p_x,  g_x);
    cudaGetSymbolAddress((void**)&p_h1, g_h1);
    cudaGetSymbolAddress((void**)&p_h2, g_h2);
    cudaGetSymbolAddress((void**)&p_cs, g_cs);
    cudaGetSymbolAddress((void**)&p_tv, g_tv);

    sched_kernel<<<1, 32>>>();
    temb_kernel<<<T_STEPS, 256>>>(w_t1, b_t1, w_t2, b_t2, w1 + 32 * H_SZ);
    copy_x_kernel<<<(B_SZ * A_SZ) / 256, 256>>>(x_init);

    dim3 g1(H_SZ / TBN, B_SZ / TBM);  // (8, 32)
    // C_state = state @ W1[48:304,:] + b1  (once)
    tf32gemm<0><<<g1, 256>>>(state, w1 + 48 * H_SZ, b1, nullptr, p_cs, B_SZ, H_SZ, S_SZ);

    for (int i = T_STEPS - 1; i >= 0; --i) {
        // h1 = mish(x @ W1[0:32,:] + g_cs + g_tv[i])
        tf32gemm<2><<<g1, 256>>>(p_x, w1, p_tv + i * H_SZ, p_cs, p_h1, B_SZ, H_SZ, A_SZ);
        // h2 = mish(h1 @ W2 + b2)
        tf32gemm<1><<<g1, 256>>>(p_h1, w2, b2, nullptr, p_h2, B_SZ, H_SZ, H_SZ);
        // h3 = mish(h2 @ W3 + b3)
        tf32gemm<1><<<g1, 256>>>(p_h2, w3, b3, nullptr, p_h1, B_SZ, H_SZ, H_SZ);
        // eps + diffusion update (fused)
        update_kernel<<<B_SZ / 32, 256>>>(wf, bf, noise, i);
    }
    clip_out_kernel<<<(B_SZ * A_SZ) / 256, 256>>>((float*)d_out);
}

// round 3
// speedup vs baseline: 2.3434x; 1.0101x over previous
#include <cuda_runtime.h>
#include <math.h>
#include <stdint.h>

#define T_STEPS 100
#define B_SZ 4096
#define A_SZ 32
#define H_SZ 1024
#define S_SZ 256

// ---------------- scratch (static device globals; no allocation) ----------------
__device__ float g_x  [B_SZ * A_SZ];          // fp32 x recurrence
__device__ float g_xr [B_SZ * A_SZ];          // tf32-rounded copy for GEMM A
__device__ float g_h1 [B_SZ * H_SZ];
__device__ float g_h2 [B_SZ * H_SZ];
__device__ float g_cs [B_SZ * H_SZ];          // state @ W1_state + b1 (fp32, epilogue add)
__device__ float g_tv [T_STEPS * H_SZ];
__device__ float g_sr [T_STEPS];
__device__ float g_srm[T_STEPS];
__device__ float g_p1 [T_STEPS];
__device__ float g_p2 [T_STEPS];
__device__ float g_sig[T_STEPS];
// pre-rounded (tf32-rna) operand copies
__device__ float g_state_r[B_SZ * S_SZ];
__device__ float g_w1x_r [A_SZ * H_SZ];
__device__ float g_w1s_r [S_SZ * H_SZ];
__device__ float g_w2_r  [H_SZ * H_SZ];
__device__ float g_w3_r  [H_SZ * H_SZ];

__device__ __forceinline__ float mishf(float v) {
    float sp = (v > 20.0f) ? v : log1pf(expf(v));
    return v * tanhf(sp);
}
__device__ __forceinline__ uint32_t f2tf32(float f) {
    uint32_t u;
    asm("cvt.rna.tf32.f32 %0, %1;" : "=r"(u) : "f"(f));
    return u;
}
__device__ __forceinline__ void cpa16(void* s, const void* g) {
    uint32_t sa = (uint32_t)__cvta_generic_to_shared(s);
    asm volatile("cp.async.cg.shared.global [%0], [%1], 16;" :: "r"(sa), "l"(g));
}
#define CP_COMMIT() asm volatile("cp.async.commit_group;")
template <int N>
__device__ __forceinline__ void cp_wait() {
    asm volatile("cp.async.wait_group %0;" :: "n"(N));
}

// ---------------- schedule precompute ----------------
__global__ void sched_kernel() {
    if (threadIdx.x != 0) return;
    float ab = 1.0f;
    for (int i = 0; i < T_STEPS; i++) {
        float beta  = 1e-4f + (0.2f - 1e-4f) * ((float)i / 99.0f);
        float alpha = 1.0f - beta;
        float abprev = ab;
        ab *= alpha;
        float one_m_ab = 1.0f - ab;
        float post_var = beta * (1.0f - abprev) / one_m_ab;
        g_sr [i] = sqrtf(1.0f / ab);
        g_srm[i] = sqrtf(1.0f / ab - 1.0f);
        g_p1 [i] = beta * sqrtf(abprev) / one_m_ab;
        g_p2 [i] = (1.0f - abprev) * sqrtf(alpha) / one_m_ab;
        g_sig[i] = sqrtf(fmaxf(post_var, 1e-20f));
    }
}

// ---------------- per-step time-embedding vector precompute ----------------
__global__ void temb_kernel(const float* __restrict__ w_t1, const float* __restrict__ b_t1,
                            const float* __restrict__ w_t2, const float* __restrict__ b_t2,
                            const float* __restrict__ w1t) {
    int i = blockIdx.x;
    int t = threadIdx.x;
    __shared__ float emb[16];
    __shared__ float e1[256];
    __shared__ float temb[16];

    if (t < 8) {
        float freq = expf((float)t * (-logf(10000.0f) / 7.0f));
        float ang  = (float)i * freq;
        emb[t]     = sinf(ang);
        emb[t + 8] = cosf(ang);
    }
    __syncthreads();
    {
        float s = b_t1[t];
        #pragma unroll
        for (int j = 0; j < 16; j++) s += emb[j] * w_t1[j * 256 + t];
        e1[t] = mishf(s);
    }
    __syncthreads();
    if (t < 16) {
        float s = b_t2[t];
        for (int p = 0; p < 256; p++) s += e1[p] * w_t2[p * 16 + t];
        temb[t] = s;
    }
    __syncthreads();
    for (int n = t; n < H_SZ; n += 256) {
        float s = 0.0f;
        #pragma unroll
        for (int q = 0; q < 16; q++) s += temb[q] * w1t[q * H_SZ + n];
        g_tv[i * H_SZ + n] = s;
    }
}

__global__ void copy_x_kernel(const float* __restrict__ x_init) {
    int idx = blockIdx.x * blockDim.x + threadIdx.x;
    float v = x_init[idx];
    g_x[idx]  = v;
    g_xr[idx] = __uint_as_float(f2tf32(v));
}
__global__ void clip_out_kernel(float* __restrict__ out) {
    int idx = blockIdx.x * blockDim.x + threadIdx.x;
    out[idx] = fminf(fmaxf(g_x[idx], -1.0f), 1.0f);
}
__global__ void round_copy_kernel(const float* __restrict__ src, float* __restrict__ dst) {
    int idx = blockIdx.x * blockDim.x + threadIdx.x;
    dst[idx] = __uint_as_float(f2tf32(src[idx]));
}

// ---------------- tf32 tensor-core GEMM, 128x128x32, cp.async 3-stage ----------------
// C[M,N] = epi( A[M,K] @ B[K,N] ),  A/B already tf32-rounded in gmem.
// EPI 0: acc + bias[n]                       (no output rounding)
// EPI 1: tf32rna( mish(acc + bias[n]) )
// EPI 2: tf32rna( mish(acc + bias[n] + add[m,n]) )
// M%128==0, N%128==0, K%32==0.
#define STAGES 3
#define BKF 32
// per-stage: A 128*32 floats, B 32*128 floats
extern __shared__ float smem_f[];

template <int EPI>
__global__ __launch_bounds__(256, 2)
void tf32gemm(const float* __restrict__ A, const float* __restrict__ Bm,
              const float* __restrict__ bias, const float* __restrict__ add,
              float* __restrict__ C, int M, int N, int K) {
    const int tid  = threadIdx.x;
    const int lane = tid & 31;
    const int warp = tid >> 5;
    const int warpM = (warp >> 2) * 64;
    const int warpN = (warp & 3) * 32;
    const int groupID = lane >> 2;       // 0..7  (== m&7 for all our A rows)
    const int tid4    = lane & 3;

    const int m0 = blockIdx.y * 128;
    const int n0 = blockIdx.x * 128;

    // cp.async thread mappings
    const int am   = tid >> 1;           // 0..127
    const int ak4b = (tid & 1) * 4;      // 0 or 4   (chunk base, +i)
    const int bk   = tid >> 3;           // 0..31
    const int bn4b = (tid & 7) * 4;      // 0,4,...,28 (chunk base, +i)

    const float* Abase = A + (size_t)(m0 + am) * K;
    const float* Bbase = Bm + (size_t)bk * N + n0;

    const int nIter = K / BKF;

    float acc[4][4][4];
    #pragma unroll
    for (int i = 0; i < 4; i++)
        #pragma unroll
        for (int j = 0; j < 4; j++)
            #pragma unroll
            for (int q = 0; q < 4; q++) acc[i][j][q] = 0.0f;

    // smem store offsets (precompute the swizzled float offsets per chunk)
    int aOff[4], bOff[4];
    #pragma unroll
    for (int i = 0; i < 4; i++) {
        int k4 = ak4b + i;
        aOff[i] = am * 32 + ((k4 ^ (am & 7)) << 2);
        int n4 = bn4b + i;
        int gsw = (n4 & 0x18) | ((2 * bk + n4) & 7);
        bOff[i] = bk * 128 + (gsw << 2);
    }

    // prologue: stages 0..STAGES-2
    #pragma unroll
    for (int s = 0; s < STAGES - 1; s++) {
        if (s < nIter) {
            float* sA = smem_f + s * 4096;
            float* sB = smem_f + STAGES * 4096 + s * 4096;
            int kk = s * BKF;
            #pragma unroll
            for (int i = 0; i < 4; i++) {
                cpa16(sA + aOff[i], Abase + kk + (ak4b + i) * 4);
                cpa16(sB + bOff[i], Bbase + (size_t)kk * N + (bn4b + i) * 4);
            }
        }
        CP_COMMIT();
    }

    // B fragment swizzle constants (independent of ks and j):
    // n4(ni) = warpN/4 + 2*ni + (groupID>>2);  g = (n4&0x18)|((2*tid4+n4)&7)
    int bFragOff[4];
    #pragma unroll
    for (int ni = 0; ni < 4; ni++) {
        int n4 = (warpN >> 2) + 2 * ni + (groupID >> 2);
        int gsw = (n4 & 0x18) | ((2 * tid4 + n4) & 7);
        bFragOff[ni] = (gsw << 2) + (groupID & 3);
    }
    // A fragment row bases
    int aRowOff[4];
    #pragma unroll
    for (int mi = 0; mi < 4; mi++)
        aRowOff[mi] = (warpM + mi * 16 + groupID) * 32 + tid4;

    for (int it = 0; it < nIter; ++it) {
        cp_wait<STAGES - 2>();
        __syncthreads();

        // issue stage it+STAGES-1 (overlaps with compute below)
        int nxt = it + STAGES - 1;
        if (nxt < nIter) {
            int buf = nxt % STAGES;
            float* sA = smem_f + buf * 4096;
            float* sB = smem_f + STAGES * 4096 + buf * 4096;
            int kk = nxt * BKF;
            #pragma unroll
            for (int i = 0; i < 4; i++) {
                cpa16(sA + aOff[i], Abase + kk + (ak4b + i) * 4);
                cpa16(sB + bOff[i], Bbase + (size_t)kk * N + (bn4b + i) * 4);
            }
        }
        CP_COMMIT();

        // compute on buffer it%STAGES
        const float* sA = smem_f + (it % STAGES) * 4096;
        const float* sB = smem_f + STAGES * 4096 + (it % STAGES) * 4096;

        #pragma unroll
        for (int ks = 0; ks < 4; ks++) {
            // A swizzled column offsets for this ks (same for every mi: m&7==groupID)
            const int swz0 = ((2 * ks)     ^ groupID) << 2;
            const int swz1 = ((2 * ks + 1) ^ groupID) << 2;
            uint32_t af[4][4], bfr[4][2];
            #pragma unroll
            for (int mi = 0; mi < 4; mi++) {
                af[mi][0] = __float_as_uint(sA[aRowOff[mi]       + swz0]);
                af[mi][1] = __float_as_uint(sA[aRowOff[mi] + 256 + swz0]);  // +8 rows = +8*32
                af[mi][2] = __float_as_uint(sA[aRowOff[mi]       + swz1]);
                af[mi][3] = __float_as_uint(sA[aRowOff[mi] + 256 + swz1]);
            }
            const int kRow0 = (8 * ks + tid4) * 128;
            const int kRow1 = kRow0 + 4 * 128;
            #pragma unroll
            for (int ni = 0; ni < 4; ni++) {
                bfr[ni][0] = __float_as_uint(sB[kRow0 + bFragOff[ni]]);
                bfr[ni][1] = __float_as_uint(sB[kRow1 + bFragOff[ni]]);
            }
            #pragma unroll
            for (int mi = 0; mi < 4; mi++)
                #pragma unroll
                for (int ni = 0; ni < 4; ni++) {
                    asm volatile(
                        "mma.sync.aligned.m16n8k8.row.col.f32.tf32.tf32.f32 "
                        "{%0,%1,%2,%3}, {%4,%5,%6,%7}, {%8,%9}, {%0,%1,%2,%3};"
                        : "+f"(acc[mi][ni][0]), "+f"(acc[mi][ni][1]),
                          "+f"(acc[mi][ni][2]), "+f"(acc[mi][ni][3])
                        : "r"(af[mi][0]), "r"(af[mi][1]), "r"(af[mi][2]), "r"(af[mi][3]),
                          "r"(bfr[ni][0]), "r"(bfr[ni][1]));
                }
        }
    }

    // epilogue
    #pragma unroll
    for (int mi = 0; mi < 4; mi++) {
        int row0 = m0 + warpM + mi * 16 + groupID;
        int row1 = row0 + 8;
        #pragma unroll
        for (int ni = 0; ni < 4; ni++) {
            int col = n0 + warpN + ni * 8 + tid4 * 2;
            float b0v = bias[col], b1v = bias[col + 1];
            float s0 = acc[mi][ni][0] + b0v;
            float s1 = acc[mi][ni][1] + b1v;
            float s2 = acc[mi][ni][2] + b0v;
            float s3 = acc[mi][ni][3] + b1v;
            if (EPI == 2) {
                s0 += add[(size_t)row0 * N + col];
                s1 += add[(size_t)row0 * N + col + 1];
                s2 += add[(size_t)row1 * N + col];
                s3 += add[(size_t)row1 * N + col + 1];
            }
            if (EPI >= 1) {
                s0 = __uint_as_float(f2tf32(mishf(s0)));
                s1 = __uint_as_float(f2tf32(mishf(s1)));
                s2 = __uint_as_float(f2tf32(mishf(s2)));
                s3 = __uint_as_float(f2tf32(mishf(s3)));
            }
            *reinterpret_cast<float2*>(C + (size_t)row0 * N + col) = make_float2(s0, s1);
            *reinterpret_cast<float2*>(C + (size_t)row1 * N + col) = make_float2(s2, s3);
        }
    }
}

// ---------------- fused final-layer GEMM (N=32) + diffusion update ----------------
__global__ __launch_bounds__(256)
void update_kernel(const float* __restrict__ wf, const float* __restrict__ bf,
                   const float* __restrict__ noise, int step) {
    __shared__ float As[32][32];
    __shared__ float Bs[32][32];
    int tid = threadIdx.x;
    int bm  = blockIdx.x * 32;
    int tx = tid & 31, ty = tid >> 5;
    int lr = tid >> 3;
    int lc = (tid & 7) * 4;

    float acc[4] = {0.f, 0.f, 0.f, 0.f};
    for (int kk = 0; kk < H_SZ; kk += 32) {
        *reinterpret_cast<float4*>(&As[lr][lc]) =
            *reinterpret_cast<const float4*>(&g_h1[(size_t)(bm + lr) * H_SZ + kk + lc]);
        *reinterpret_cast<float4*>(&Bs[lr][lc]) =
            *reinterpret_cast<const float4*>(wf + (size_t)(kk + lr) * 32 + lc);
        __syncthreads();
        #pragma unroll
        for (int k = 0; k < 32; k++) {
            float b = Bs[k][tx];
            #pragma unroll
            for (int r = 0; r < 4; r++)
                acc[r] = fmaf(As[ty * 4 + r][k], b, acc[r]);
        }
        __syncthreads();
    }

    float sr  = g_sr[step], srm = g_srm[step];
    float p1  = g_p1[step], p2  = g_p2[step];
    float sig = (step != 0) ? g_sig[step] : 0.0f;
    const float* z = noise + (size_t)(T_STEPS - 1 - step) * B_SZ * A_SZ;

    #pragma unroll
    for (int r = 0; r < 4; r++) {
        int m = bm + ty * 4 + r;
        float eps = acc[r] + bf[tx];
        float xo  = g_x[(size_t)m * A_SZ + tx];
        float xr  = fminf(fmaxf(sr * xo - srm * eps, -1.0f), 1.0f);
        float xn  = p1 * xr + p2 * xo + sig * z[(size_t)m * A_SZ + tx];
        g_x [(size_t)m * A_SZ + tx] = xn;
        g_xr[(size_t)m * A_SZ + tx] = __uint_as_float(f2tf32(xn));
    }
}

// ---------------- launch ----------------
extern "C" void kernel_launch(void* const* d_in, const int* in_sizes, int n_in,
                              void* d_out, int out_size) {
    const float* state  = (const float*)d_in[0];
    const float* w_t1   = (const float*)d_in[1];
    const float* b_t1   = (const float*)d_in[2];
    const float* w_t2   = (const float*)d_in[3];
    const float* b_t2   = (const float*)d_in[4];
    const float* w1     = (const float*)d_in[5];
    const float* b1     = (const float*)d_in[6];
    const float* w2     = (const float*)d_in[7];
    const float* b2     = (const float*)d_in[8];
    const float* w3     = (const float*)d_in[9];
    const float* b3     = (const float*)d_in[10];
    const float* wf     = (const float*)d_in[11];
    const float* bf     = (const float*)d_in[12];
    const float* x_init = (const float*)d_in[13];
    const float* noise  = (const float*)d_in[14];

    float *p_xr, *p_h1, *p_h2, *p_cs, *p_tv;
    float *p_state_r, *p_w1x_r, *p_w1s_r, *p_w2_r, *p_w3_r;
    cudaGetSymbolAddress((void**)&p_xr, g_xr);
    cudaGetSymbolAddress((void**)&p_h1, g_h1);
    cudaGetSymbolAddress((void**)&p_h2, g_h2);
    cudaGetSymbolAddress((void**)&p_cs, g_cs);
    cudaGetSymbolAddress((void**)&p_tv, g_tv);
    cudaGetSymbolAddress((void**)&p_state_r, g_state_r);
    cudaGetSymbolAddress((void**)&p_w1x_r,  g_w1x_r);
    cudaGetSymbolAddress((void**)&p_w1s_r,  g_w1s_r);
    cudaGetSymbolAddress((void**)&p_w2_r,   g_w2_r);
    cudaGetSymbolAddress((void**)&p_w3_r,   g_w3_r);

    const int SMEM = STAGES * 2 * 4096 * sizeof(float);  // 98304
    cudaFuncSetAttribute(tf32gemm<0>, cudaFuncAttributeMaxDynamicSharedMemorySize, SMEM);
    cudaFuncSetAttribute(tf32gemm<1>, cudaFuncAttributeMaxDynamicSharedMemorySize, SMEM);
    cudaFuncSetAttribute(tf32gemm<2>, cudaFuncAttributeMaxDynamicSharedMemorySize, SMEM);

    sched_kernel<<<1, 32>>>();
    temb_kernel<<<T_STEPS, 256>>>(w_t1, b_t1, w_t2, b_t2, w1 + 32 * H_SZ);
    copy_x_kernel<<<(B_SZ * A_SZ) / 256, 256>>>(x_init);

    // one-time tf32 pre-rounding of GEMM operands
    round_copy_kernel<<<(B_SZ * S_SZ) / 256, 256>>>(state, p_state_r);
    round_copy_kernel<<<(A_SZ * H_SZ) / 256, 256>>>(w1, p_w1x_r);
    round_copy_kernel<<<(S_SZ * H_SZ) / 256, 256>>>(w1 + 48 * H_SZ, p_w1s_r);
    round_copy_kernel<<<(H_SZ * H_SZ) / 256, 256>>>(w2, p_w2_r);
    round_copy_kernel<<<(H_SZ * H_SZ) / 256, 256>>>(w3, p_w3_r);

    dim3 g1(H_SZ / 128, B_SZ / 128);  // (8, 32)
    // C_state = state @ W1[48:304,:] + b1  (once, fp32 output)
    tf32gemm<0><<<g1, 256, SMEM>>>(p_state_r, p_w1s_r, b1, nullptr, p_cs, B_SZ, H_SZ, S_SZ);

    for (int i = T_STEPS - 1; i >= 0; --i) {
        // h1 = mish(x @ W1[0:32,:] + g_cs + g_tv[i])
        tf32gemm<2><<<g1, 256, SMEM>>>(p_xr, p_w1x_r, p_tv + i * H_SZ, p_cs, p_h1, B_SZ, H_SZ, A_SZ);
        // h2 = mish(h1 @ W2 + b2)
        tf32gemm<1><<<g1, 256, SMEM>>>(p_h1, p_w2_r, b2, nullptr, p_h2, B_SZ, H_SZ, H_SZ);
        // h3 = mish(h2 @ W3 + b3)
        tf32gemm<1><<<g1, 256, SMEM>>>(p_h2, p_w3_r, b3, nullptr, p_h1, B_SZ, H_SZ, H_SZ);
        // eps + diffusion update (fused)
        update_kernel<<<B_SZ / 32, 256>>>(wf, bf, noise, i);
    }
    clip_out_kernel<<<(B_SZ * A_SZ) / 256, 256>>>((float*)d_out);
}

// round 5
// speedup vs baseline: 3.7704x; 1.6090x over previous
#include <cuda_runtime.h>
#include <cuda_fp16.h>
#include <math.h>
#include <stdint.h>

#define T_STEPS 100
#define B_SZ 4096
#define A_SZ 32
#define H_SZ 1024
#define S_SZ 256

// ---------------- scratch (static device globals; no allocation) ----------------
__device__ float  g_x  [B_SZ * A_SZ];
__device__ float  g_xr [B_SZ * A_SZ];          // tf32-rounded x (layer-1 A operand)
__device__ __half g_h1h[B_SZ * H_SZ];
__device__ __half g_h2h[B_SZ * H_SZ];
__device__ float  g_cs [B_SZ * H_SZ];          // state @ W1_state + b1 (fp32)
__device__ float  g_tv [T_STEPS * H_SZ];
__device__ float  g_sr [T_STEPS];
__device__ float  g_srm[T_STEPS];
__device__ float  g_p1 [T_STEPS];
__device__ float  g_p2 [T_STEPS];
__device__ float  g_sig[T_STEPS];
// prepared operands
__device__ float  g_w1x_r  [A_SZ * H_SZ];      // layer1 B (tf32-rounded fp32)
__device__ __half g_state_h[B_SZ * S_SZ];      // [M,K] half
__device__ __half g_w1st_h [H_SZ * S_SZ];      // W1_state^T [N,K] half
__device__ __half g_w2t_h  [H_SZ * H_SZ];      // W2^T [N,K] half
__device__ __half g_w3t_h  [H_SZ * H_SZ];      // W3^T [N,K] half

// exact mish: tanh(softplus(v)) = (u^2-1)/(u^2+1), u = 1+e^v
__device__ __forceinline__ float mishf(float v) {
    float e  = expf(fminf(v, 30.0f));
    float u  = 1.0f + e;
    float u2 = u * u;
    return v * __fdividef(u2 - 1.0f, u2 + 1.0f);
}
__device__ __forceinline__ uint32_t f2tf32(float f) {
    uint32_t u;
    asm("cvt.rna.tf32.f32 %0, %1;" : "=r"(u) : "f"(f));
    return u;
}
__device__ __forceinline__ void cpa16(uint32_t s, const void* g) {
    asm volatile("cp.async.cg.shared.global [%0], [%1], 16;" :: "r"(s), "l"(g));
}
#define CP_COMMIT() asm volatile("cp.async.commit_group;")
template <int N_>
__device__ __forceinline__ void cp_wait() {
    asm volatile("cp.async.wait_group %0;" :: "n"(N_));
}
__device__ __forceinline__ uint32_t smem_u32(const void* p) {
    uint32_t a;
    asm("{ .reg .u64 t; cvta.to.shared.u64 t, %1; cvt.u32.u64 %0, t; }" : "=r"(a) : "l"(p));
    return a;
}
__device__ __forceinline__ void ldm4(uint32_t* r, uint32_t a) {
    asm volatile("ldmatrix.sync.aligned.m8n8.x4.shared.b16 {%0,%1,%2,%3}, [%4];"
                 : "=r"(r[0]), "=r"(r[1]), "=r"(r[2]), "=r"(r[3]) : "r"(a));
}
__device__ __forceinline__ void mma16816(float* d, const uint32_t* a, uint32_t b0, uint32_t b1) {
    asm volatile(
        "mma.sync.aligned.m16n8k16.row.col.f32.f16.f16.f32 "
        "{%0,%1,%2,%3}, {%4,%5,%6,%7}, {%8,%9}, {%0,%1,%2,%3};"
        : "+f"(d[0]), "+f"(d[1]), "+f"(d[2]), "+f"(d[3])
        : "r"(a[0]), "r"(a[1]), "r"(a[2]), "r"(a[3]), "r"(b0), "r"(b1));
}

// ---------------- schedule precompute ----------------
__global__ void sched_kernel() {
    if (threadIdx.x != 0) return;
    float ab = 1.0f;
    for (int i = 0; i < T_STEPS; i++) {
        float beta  = 1e-4f + (0.2f - 1e-4f) * ((float)i / 99.0f);
        float alpha = 1.0f - beta;
        float abprev = ab;
        ab *= alpha;
        float one_m_ab = 1.0f - ab;
        float post_var = beta * (1.0f - abprev) / one_m_ab;
        g_sr [i] = sqrtf(1.0f / ab);
        g_srm[i] = sqrtf(1.0f / ab - 1.0f);
        g_p1 [i] = beta * sqrtf(abprev) / one_m_ab;
        g_p2 [i] = (1.0f - abprev) * sqrtf(alpha) / one_m_ab;
        g_sig[i] = sqrtf(fmaxf(post_var, 1e-20f));
    }
}

// ---------------- per-step time-embedding vector precompute ----------------
__global__ void temb_kernel(const float* __restrict__ w_t1, const float* __restrict__ b_t1,
                            const float* __restrict__ w_t2, const float* __restrict__ b_t2,
                            const float* __restrict__ w1t) {
    int i = blockIdx.x;
    int t = threadIdx.x;
    __shared__ float emb[16];
    __shared__ float e1[256];
    __shared__ float temb[16];

    if (t < 8) {
        float freq = expf((float)t * (-logf(10000.0f) / 7.0f));
        float ang  = (float)i * freq;
        emb[t]     = sinf(ang);
        emb[t + 8] = cosf(ang);
    }
    __syncthreads();
    {
        float s = b_t1[t];
        #pragma unroll
        for (int j = 0; j < 16; j++) s += emb[j] * w_t1[j * 256 + t];
        e1[t] = mishf(s);
    }
    __syncthreads();
    if (t < 16) {
        float s = b_t2[t];
        for (int p = 0; p < 256; p++) s += e1[p] * w_t2[p * 16 + t];
        temb[t] = s;
    }
    __syncthreads();
    for (int n = t; n < H_SZ; n += 256) {
        float s = 0.0f;
        #pragma unroll
        for (int q = 0; q < 16; q++) s += temb[q] * w1t[q * H_SZ + n];
        g_tv[i * H_SZ + n] = s;
    }
}

__global__ void copy_x_kernel(const float* __restrict__ x_init) {
    int idx = blockIdx.x * blockDim.x + threadIdx.x;
    float v = x_init[idx];
    g_x[idx]  = v;
    g_xr[idx] = __uint_as_float(f2tf32(v));
}
__global__ void clip_out_kernel(float* __restrict__ out) {
    int idx = blockIdx.x * blockDim.x + threadIdx.x;
    out[idx] = fminf(fmaxf(g_x[idx], -1.0f), 1.0f);
}
__global__ void round_copy_kernel(const float* __restrict__ src, float* __restrict__ dst) {
    int idx = blockIdx.x * blockDim.x + threadIdx.x;
    dst[idx] = __uint_as_float(f2tf32(src[idx]));
}
__global__ void half_copy_kernel(const float* __restrict__ src, __half* __restrict__ dst) {
    int idx = blockIdx.x * blockDim.x + threadIdx.x;
    dst[idx] = __float2half(src[idx]);
}
// dst[N][K] = half(src[K][N])
__global__ void transpose_half_kernel(const float* __restrict__ src, __half* __restrict__ dst,
                                      int Kdim, int Ndim) {
    __shared__ float tile[32][33];
    int kb = blockIdx.y * 32, nb = blockIdx.x * 32;
    int tx = threadIdx.x, ty = threadIdx.y;  // 32 x 8
    #pragma unroll
    for (int j = 0; j < 32; j += 8)
        tile[ty + j][tx] = src[(size_t)(kb + ty + j) * Ndim + nb + tx];
    __syncthreads();
    #pragma unroll
    for (int j = 0; j < 32; j += 8)
        dst[(size_t)(nb + ty + j) * Kdim + kb + tx] = __float2half(tile[tx][ty + j]);
}

// ================= fp16 mma.sync GEMM: C = epi(A[M,K]h @ Bt[N,K]h^T) =================
// Tile 128x256, BK=64 (128B rows, XOR-8 swizzle), 3-stage cp.async, ldmatrix.x4.
// 8 warps, warptile 64x64.  EPI 0: float out, +bias.  EPI 1: half out, mish(+bias).
#define HG_STG 49152            // per stage: A 128*64*2 + B 256*64*2 = 16KB+32KB
#define HG_SMEM (3 * HG_STG)    // 147456

__device__ __forceinline__ void hg_fill(uint32_t sAu, uint32_t sBu,
                                        const __half* Ag, const __half* Bg,
                                        int K, int kk, int tid) {
    int r = tid >> 1, cb = (tid & 1) * 4;
    #pragma unroll
    for (int i = 0; i < 4; i++) {
        int c = cb + i;
        cpa16(sAu + r * 128 + ((c ^ (r & 7)) << 4), Ag + (size_t)r * K + kk + c * 8);
    }
    #pragma unroll
    for (int i = 0; i < 8; i++) {
        cpa16(sBu + tid * 128 + ((i ^ (tid & 7)) << 4), Bg + (size_t)tid * K + kk + i * 8);
    }
}

template <int EPI>
__global__ __launch_bounds__(256, 1)
void hgemm(const __half* __restrict__ A, const __half* __restrict__ Bt,
           const float* __restrict__ bias, void* __restrict__ Cv,
           int K, int N) {
    extern __shared__ __align__(16) char smem_raw[];
    const uint32_t sbase = smem_u32(smem_raw);
    const int tid  = threadIdx.x;
    const int lane = tid & 31;
    const int warp = tid >> 5;
    const int warpM = (warp >> 2) * 64;
    const int warpN = (warp & 3) * 64;
    const int g  = lane >> 2;
    const int t4 = lane & 3;
    const int m0 = blockIdx.y * 128;
    const int n0 = blockIdx.x * 256;
    const __half* Ag = A  + (size_t)m0 * K;
    const __half* Bg = Bt + (size_t)n0 * K;
    const int nIter = K / 64;

    float acc[4][8][4];
    #pragma unroll
    for (int i = 0; i < 4; i++)
        #pragma unroll
        for (int j = 0; j < 8; j++)
            #pragma unroll
            for (int q = 0; q < 4; q++) acc[i][j][q] = 0.0f;

    hg_fill(sbase, sbase + 16384, Ag, Bg, K, 0, tid);
    CP_COMMIT();
    hg_fill(sbase + HG_STG, sbase + HG_STG + 16384, Ag, Bg, K, 64, tid);
    CP_COMMIT();

    // ldmatrix per-lane address components
    const int lo7  = lane & 7;
    const int aRow = lane & 15;            // A: row within 16
    const int aHi  = lane >> 4;            // A: k-chunk select
    const int bRow = (lane & 7) + ((lane >> 4) << 3);   // B: row within 16 (n)
    const int bHi  = (lane >> 3) & 1;      // B: k-chunk select

    for (int it = 0; it < nIter; ++it) {
        cp_wait<1>();
        __syncthreads();
        int nxt = it + 2;
        if (nxt < nIter) {
            uint32_t sf = sbase + (nxt % 3) * HG_STG;
            hg_fill(sf, sf + 16384, Ag, Bg, K, nxt * 64, tid);
        }
        CP_COMMIT();

        const uint32_t sAu = sbase + (it % 3) * HG_STG;
        const uint32_t sBu = sAu + 16384;

        #pragma unroll
        for (int ks = 0; ks < 4; ks++) {
            uint32_t a[4][4], b[4][4];
            #pragma unroll
            for (int mi = 0; mi < 4; mi++) {
                int row = warpM + mi * 16 + aRow;
                ldm4(a[mi], sAu + row * 128 + (((2 * ks + aHi) ^ lo7) << 4));
            }
            #pragma unroll
            for (int p = 0; p < 4; p++) {
                int row = warpN + p * 16 + bRow;
                ldm4(b[p], sBu + row * 128 + (((2 * ks + bHi) ^ lo7) << 4));
            }
            #pragma unroll
            for (int mi = 0; mi < 4; mi++)
                #pragma unroll
                for (int p = 0; p < 4; p++) {
                    mma16816(acc[mi][2 * p],     a[mi], b[p][0], b[p][1]);
                    mma16816(acc[mi][2 * p + 1], a[mi], b[p][2], b[p][3]);
                }
        }
    }

    // epilogue
    float2 bv[8];
    #pragma unroll
    for (int ni = 0; ni < 8; ni++) {
        int col = n0 + warpN + ni * 8 + t4 * 2;
        bv[ni] = make_float2(bias[col], bias[col + 1]);
    }
    #pragma unroll
    for (int mi = 0; mi < 4; mi++) {
        int row0 = m0 + warpM + mi * 16 + g;
        int row1 = row0 + 8;
        #pragma unroll
        for (int ni = 0; ni < 8; ni++) {
            int col = n0 + warpN + ni * 8 + t4 * 2;
            float s0 = acc[mi][ni][0] + bv[ni].x;
            float s1 = acc[mi][ni][1] + bv[ni].y;
            float s2 = acc[mi][ni][2] + bv[ni].x;
            float s3 = acc[mi][ni][3] + bv[ni].y;
            if (EPI == 1) {
                s0 = mishf(s0); s1 = mishf(s1); s2 = mishf(s2); s3 = mishf(s3);
                __half* C = (__half*)Cv;
                *reinterpret_cast<__half2*>(C + (size_t)row0 * N + col) = __floats2half2_rn(s0, s1);
                *reinterpret_cast<__half2*>(C + (size_t)row1 * N + col) = __floats2half2_rn(s2, s3);
            } else {
                float* C = (float*)Cv;
                *reinterpret_cast<float2*>(C + (size_t)row0 * N + col) = make_float2(s0, s1);
                *reinterpret_cast<float2*>(C + (size_t)row1 * N + col) = make_float2(s2, s3);
            }
        }
    }
}

// ---------------- layer-1 tf32 mma.sync GEMM (K=32), 128x128, half out ----------------
#define STAGES 3
#define BKF 32
extern __shared__ float smem_f[];

__global__ __launch_bounds__(256, 2)
void l1gemm(const float* __restrict__ A, const float* __restrict__ Bm,
            const float* __restrict__ bias, const float* __restrict__ add,
            __half* __restrict__ C, int M, int N, int K) {
    const int tid  = threadIdx.x;
    const int lane = tid & 31;
    const int warp = tid >> 5;
    const int warpM = (warp >> 2) * 64;
    const int warpN = (warp & 3) * 32;
    const int groupID = lane >> 2;
    const int tid4    = lane & 3;

    const int m0 = blockIdx.y * 128;
    const int n0 = blockIdx.x * 128;

    const int am   = tid >> 1;
    const int ak4b = (tid & 1) * 4;
    const int bk   = tid >> 3;
    const int bn4b = (tid & 7) * 4;

    const float* Abase = A + (size_t)(m0 + am) * K;
    const float* Bbase = Bm + (size_t)bk * N + n0;

    const int nIter = K / BKF;

    float acc[4][4][4];
    #pragma unroll
    for (int i = 0; i < 4; i++)
        #pragma unroll
        for (int j = 0; j < 4; j++)
            #pragma unroll
            for (int q = 0; q < 4; q++) acc[i][j][q] = 0.0f;

    int aOff[4], bOff[4];
    #pragma unroll
    for (int i = 0; i < 4; i++) {
        int k4 = ak4b + i;
        aOff[i] = am * 32 + ((k4 ^ (am & 7)) << 2);
        int n4 = bn4b + i;
        int gsw = (n4 & 0x18) | ((2 * bk + n4) & 7);
        bOff[i] = bk * 128 + (gsw << 2);
    }

    #pragma unroll
    for (int s = 0; s < STAGES - 1; s++) {
        if (s < nIter) {
            float* sA = smem_f + s * 4096;
            float* sB = smem_f + STAGES * 4096 + s * 4096;
            int kk = s * BKF;
            #pragma unroll
            for (int i = 0; i < 4; i++) {
                cpa16(smem_u32(sA + aOff[i]), Abase + kk + (ak4b + i) * 4);
                cpa16(smem_u32(sB + bOff[i]), Bbase + (size_t)kk * N + (bn4b + i) * 4);
            }
        }
        CP_COMMIT();
    }

    int bFragOff[4];
    #pragma unroll
    for (int ni = 0; ni < 4; ni++) {
        int n4 = (warpN >> 2) + 2 * ni + (groupID >> 2);
        int gsw = (n4 & 0x18) | ((2 * tid4 + n4) & 7);
        bFragOff[ni] = (gsw << 2) + (groupID & 3);
    }
    int aRowOff[4];
    #pragma unroll
    for (int mi = 0; mi < 4; mi++)
        aRowOff[mi] = (warpM + mi * 16 + groupID) * 32 + tid4;

    for (int it = 0; it < nIter; ++it) {
        cp_wait<STAGES - 2>();
        __syncthreads();

        int nxt = it + STAGES - 1;
        if (nxt < nIter) {
            int buf = nxt % STAGES;
            float* sA = smem_f + buf * 4096;
            float* sB = smem_f + STAGES * 4096 + buf * 4096;
            int kk = nxt * BKF;
            #pragma unroll
            for (int i = 0; i < 4; i++) {
                cpa16(smem_u32(sA + aOff[i]), Abase + kk + (ak4b + i) * 4);
                cpa16(smem_u32(sB + bOff[i]), Bbase + (size_t)kk * N + (bn4b + i) * 4);
            }
        }
        CP_COMMIT();

        const float* sA = smem_f + (it % STAGES) * 4096;
        const float* sB = smem_f + STAGES * 4096 + (it % STAGES) * 4096;

        #pragma unroll
        for (int ks = 0; ks < 4; ks++) {
            const int swz0 = ((2 * ks)     ^ groupID) << 2;
            const int swz1 = ((2 * ks + 1) ^ groupID) << 2;
            uint32_t af[4][4], bfr[4][2];
            #pragma unroll
            for (int mi = 0; mi < 4; mi++) {
                af[mi][0] = __float_as_uint(sA[aRowOff[mi]       + swz0]);
                af[mi][1] = __float_as_uint(sA[aRowOff[mi] + 256 + swz0]);
                af[mi][2] = __float_as_uint(sA[aRowOff[mi]       + swz1]);
                af[mi][3] = __float_as_uint(sA[aRowOff[mi] + 256 + swz1]);
            }
            const int kRow0 = (8 * ks + tid4) * 128;
            const int kRow1 = kRow0 + 4 * 128;
            #pragma unroll
            for (int ni = 0; ni < 4; ni++) {
                bfr[ni][0] = __float_as_uint(sB[kRow0 + bFragOff[ni]]);
                bfr[ni][1] = __float_as_uint(sB[kRow1 + bFragOff[ni]]);
            }
            #pragma unroll
            for (int mi = 0; mi < 4; mi++)
                #pragma unroll
                for (int ni = 0; ni < 4; ni++) {
                    asm volatile(
                        "mma.sync.aligned.m16n8k8.row.col.f32.tf32.tf32.f32 "
                        "{%0,%1,%2,%3}, {%4,%5,%6,%7}, {%8,%9}, {%0,%1,%2,%3};"
                        : "+f"(acc[mi][ni][0]), "+f"(acc[mi][ni][1]),
                          "+f"(acc[mi][ni][2]), "+f"(acc[mi][ni][3])
                        : "r"(af[mi][0]), "r"(af[mi][1]), "r"(af[mi][2]), "r"(af[mi][3]),
                          "r"(bfr[ni][0]), "r"(bfr[ni][1]));
                }
        }
    }

    #pragma unroll
    for (int mi = 0; mi < 4; mi++) {
        int row0 = m0 + warpM + mi * 16 + groupID;
        int row1 = row0 + 8;
        #pragma unroll
        for (int ni = 0; ni < 4; ni++) {
            int col = n0 + warpN + ni * 8 + tid4 * 2;
            float b0v = bias[col], b1v = bias[col + 1];
            float s0 = acc[mi][ni][0] + b0v + add[(size_t)row0 * N + col];
            float s1 = acc[mi][ni][1] + b1v + add[(size_t)row0 * N + col + 1];
            float s2 = acc[mi][ni][2] + b0v + add[(size_t)row1 * N + col];
            float s3 = acc[mi][ni][3] + b1v + add[(size_t)row1 * N + col + 1];
            s0 = mishf(s0); s1 = mishf(s1); s2 = mishf(s2); s3 = mishf(s3);
            *reinterpret_cast<__half2*>(C + (size_t)row0 * N + col) = __floats2half2_rn(s0, s1);
            *reinterpret_cast<__half2*>(C + (size_t)row1 * N + col) = __floats2half2_rn(s2, s3);
        }
    }
}

// ---------------- fused final-layer GEMM (N=32) + diffusion update ----------------
__global__ __launch_bounds__(256)
void update_kernel(const float* __restrict__ wf, const float* __restrict__ bf,
                   const float* __restrict__ noise, int step) {
    __shared__ float As[32][32];
    __shared__ float Bs[32][32];
    int tid = threadIdx.x;
    int bm  = blockIdx.x * 32;
    int tx = tid & 31, ty = tid >> 5;
    int lr = tid >> 3;
    int lc = (tid & 7) * 4;

    float acc[4] = {0.f, 0.f, 0.f, 0.f};
    for (int kk = 0; kk < H_SZ; kk += 32) {
        {
            const __half2* hp = reinterpret_cast<const __half2*>(
                &g_h1h[(size_t)(bm + lr) * H_SZ + kk + lc]);
            float2 f0 = __half22float2(hp[0]);
            float2 f1 = __half22float2(hp[1]);
            As[lr][lc]     = f0.x; As[lr][lc + 1] = f0.y;
            As[lr][lc + 2] = f1.x; As[lr][lc + 3] = f1.y;
        }
        *reinterpret_cast<float4*>(&Bs[lr][lc]) =
            *reinterpret_cast<const float4*>(wf + (size_t)(kk + lr) * 32 + lc);
        __syncthreads();
        #pragma unroll
        for (int k = 0; k < 32; k++) {
            float b = Bs[k][tx];
            #pragma unroll
            for (int r = 0; r < 4; r++)
                acc[r] = fmaf(As[ty * 4 + r][k], b, acc[r]);
        }
        __syncthreads();
    }

    float sr  = g_sr[step], srm = g_srm[step];
    float p1  = g_p1[step], p2  = g_p2[step];
    float sig = (step != 0) ? g_sig[step] : 0.0f;
    const float* z = noise + (size_t)(T_STEPS - 1 - step) * B_SZ * A_SZ;

    #pragma unroll
    for (int r = 0; r < 4; r++) {
        int m = bm + ty * 4 + r;
        float eps = acc[r] + bf[tx];
        float xo  = g_x[(size_t)m * A_SZ + tx];
        float xr  = fminf(fmaxf(sr * xo - srm * eps, -1.0f), 1.0f);
        float xn  = p1 * xr + p2 * xo + sig * z[(size_t)m * A_SZ + tx];
        g_x [(size_t)m * A_SZ + tx] = xn;
        g_xr[(size_t)m * A_SZ + tx] = __uint_as_float(f2tf32(xn));
    }
}

// ---------------- launch ----------------
extern "C" void kernel_launch(void* const* d_in, const int* in_sizes, int n_in,
                              void* d_out, int out_size) {
    const float* state  = (const float*)d_in[0];
    const float* w_t1   = (const float*)d_in[1];
    const float* b_t1   = (const float*)d_in[2];
    const float* w_t2   = (const float*)d_in[3];
    const float* b_t2   = (const float*)d_in[4];
    const float* w1     = (const float*)d_in[5];
    const float* b1     = (const float*)d_in[6];
    const float* w2     = (const float*)d_in[7];
    const float* b2     = (const float*)d_in[8];
    const float* w3     = (const float*)d_in[9];
    const float* b3     = (const float*)d_in[10];
    const float* wf     = (const float*)d_in[11];
    const float* bf     = (const float*)d_in[12];
    const float* x_init = (const float*)d_in[13];
    const float* noise  = (const float*)d_in[14];

    float *p_xr, *p_cs, *p_tv, *p_w1x_r;
    __half *p_h1h, *p_h2h, *p_state_h, *p_w1st_h, *p_w2t_h, *p_w3t_h;
    cudaGetSymbolAddress((void**)&p_xr,     g_xr);
    cudaGetSymbolAddress((void**)&p_cs,     g_cs);
    cudaGetSymbolAddress((void**)&p_tv,     g_tv);
    cudaGetSymbolAddress((void**)&p_w1x_r,  g_w1x_r);
    cudaGetSymbolAddress((void**)&p_h1h,    g_h1h);
    cudaGetSymbolAddress((void**)&p_h2h,    g_h2h);
    cudaGetSymbolAddress((void**)&p_state_h, g_state_h);
    cudaGetSymbolAddress((void**)&p_w1st_h, g_w1st_h);
    cudaGetSymbolAddress((void**)&p_w2t_h,  g_w2t_h);
    cudaGetSymbolAddress((void**)&p_w3t_h,  g_w3t_h);

    const int L1_SMEM = STAGES * 2 * 4096 * sizeof(float);  // 98304
    cudaFuncSetAttribute(l1gemm, cudaFuncAttributeMaxDynamicSharedMemorySize, L1_SMEM);
    cudaFuncSetAttribute(hgemm<0>, cudaFuncAttributeMaxDynamicSharedMemorySize, HG_SMEM);
    cudaFuncSetAttribute(hgemm<1>, cudaFuncAttributeMaxDynamicSharedMemorySize, HG_SMEM);

    sched_kernel<<<1, 32>>>();
    temb_kernel<<<T_STEPS, 256>>>(w_t1, b_t1, w_t2, b_t2, w1 + 32 * H_SZ);
    copy_x_kernel<<<(B_SZ * A_SZ) / 256, 256>>>(x_init);

    // one-time operand prep
    round_copy_kernel<<<(A_SZ * H_SZ) / 256, 256>>>(w1, p_w1x_r);
    half_copy_kernel<<<(B_SZ * S_SZ) / 256, 256>>>(state, p_state_h);
    {
        dim3 blk(32, 8);
        transpose_half_kernel<<<dim3(H_SZ / 32, S_SZ / 32), blk>>>(w1 + 48 * H_SZ, p_w1st_h, S_SZ, H_SZ);
        transpose_half_kernel<<<dim3(H_SZ / 32, H_SZ / 32), blk>>>(w2, p_w2t_h, H_SZ, H_SZ);
        transpose_half_kernel<<<dim3(H_SZ / 32, H_SZ / 32), blk>>>(w3, p_w3t_h, H_SZ, H_SZ);
    }

    dim3 gh(H_SZ / 256, B_SZ / 128);    // (4, 32) = 128 CTAs, single wave
    dim3 gl1(H_SZ / 128, B_SZ / 128);   // (8, 32)

    // C_state = state @ W1_state + b1  (once, fp32 out)
    hgemm<0><<<gh, 256, HG_SMEM>>>(p_state_h, p_w1st_h, b1, p_cs, S_SZ, H_SZ);

    for (int i = T_STEPS - 1; i >= 0; --i) {
        // h1 = mish(x @ W1x + cs + tv[i])   (tf32 path, K=32, half out)
        l1gemm<<<gl1, 256, L1_SMEM>>>(p_xr, p_w1x_r, p_tv + i * H_SZ, p_cs, p_h1h, B_SZ, H_SZ, A_SZ);
        // h2 = mish(h1 @ W2 + b2)   (fp16 mma)
        hgemm<1><<<gh, 256, HG_SMEM>>>(p_h1h, p_w2t_h, b2, p_h2h, H_SZ, H_SZ);
        // h3 = mish(h2 @ W3 + b3)   (fp16 mma)
        hgemm<1><<<gh, 256, HG_SMEM>>>(p_h2h, p_w3t_h, b3, p_h1h, H_SZ, H_SZ);
        // eps + diffusion update (fused)
        update_kernel<<<B_SZ / 32, 256>>>(wf, bf, noise, i);
    }
    clip_out_kernel<<<(B_SZ * A_SZ) / 256, 256>>>((float*)d_out);
}

// round 6
// speedup vs baseline: 4.2274x; 1.1212x over previous
#include <cuda_runtime.h>
#include <cuda_fp16.h>
#include <math.h>
#include <stdint.h>

#define T_STEPS 100
#define B_SZ 4096
#define A_SZ 32
#define H_SZ 1024
#define S_SZ 256

// ---------------- scratch (static device globals; no allocation) ----------------
__device__ float  g_x  [B_SZ * A_SZ];
__device__ float  g_xr [B_SZ * A_SZ];          // tf32-rounded x (layer-1 A operand)
__device__ __half g_h1h[B_SZ * H_SZ];
__device__ __half g_h2h[B_SZ * H_SZ];
__device__ float  g_cs [B_SZ * H_SZ];          // state @ W1_state + b1 (fp32)
__device__ float  g_tv [T_STEPS * H_SZ];
__device__ float  g_sr [T_STEPS];
__device__ float  g_srm[T_STEPS];
__device__ float  g_p1 [T_STEPS];
__device__ float  g_p2 [T_STEPS];
__device__ float  g_sig[T_STEPS];
// prepared operands
__device__ float  g_w1x_r  [A_SZ * H_SZ];      // layer1 B (tf32-rounded fp32)
__device__ __half g_state_h[B_SZ * S_SZ];      // [M,K] half
__device__ __half g_w1st_h [H_SZ * S_SZ];      // W1_state^T [N,K] half
__device__ __half g_w2t_h  [H_SZ * H_SZ];      // W2^T [N,K] half
__device__ __half g_w3t_h  [H_SZ * H_SZ];      // W3^T [N,K] half

// exact mish: tanh(softplus(v)) = (u^2-1)/(u^2+1), u = 1+e^v
__device__ __forceinline__ float mishf(float v) {
    float e  = expf(fminf(v, 30.0f));
    float u  = 1.0f + e;
    float u2 = u * u;
    return v * __fdividef(u2 - 1.0f, u2 + 1.0f);
}
__device__ __forceinline__ uint32_t f2tf32(float f) {
    uint32_t u;
    asm("cvt.rna.tf32.f32 %0, %1;" : "=r"(u) : "f"(f));
    return u;
}
__device__ __forceinline__ void cpa16(uint32_t s, const void* g) {
    asm volatile("cp.async.cg.shared.global [%0], [%1], 16;" :: "r"(s), "l"(g));
}
#define CP_COMMIT() asm volatile("cp.async.commit_group;")
template <int N_>
__device__ __forceinline__ void cp_wait() {
    asm volatile("cp.async.wait_group %0;" :: "n"(N_));
}
__device__ __forceinline__ uint32_t smem_u32(const void* p) {
    uint32_t a;
    asm("{ .reg .u64 t; cvta.to.shared.u64 t, %1; cvt.u32.u64 %0, t; }" : "=r"(a) : "l"(p));
    return a;
}
__device__ __forceinline__ void ldm4(uint32_t* r, uint32_t a) {
    asm volatile("ldmatrix.sync.aligned.m8n8.x4.shared.b16 {%0,%1,%2,%3}, [%4];"
                 : "=r"(r[0]), "=r"(r[1]), "=r"(r[2]), "=r"(r[3]) : "r"(a));
}
__device__ __forceinline__ void mma16816(float* d, const uint32_t* a, uint32_t b0, uint32_t b1) {
    asm volatile(
        "mma.sync.aligned.m16n8k16.row.col.f32.f16.f16.f32 "
        "{%0,%1,%2,%3}, {%4,%5,%6,%7}, {%8,%9}, {%0,%1,%2,%3};"
        : "+f"(d[0]), "+f"(d[1]), "+f"(d[2]), "+f"(d[3])
        : "r"(a[0]), "r"(a[1]), "r"(a[2]), "r"(a[3]), "r"(b0), "r"(b1));
}

// ---------------- schedule precompute ----------------
__global__ void sched_kernel() {
    if (threadIdx.x != 0) return;
    float ab = 1.0f;
    for (int i = 0; i < T_STEPS; i++) {
        float beta  = 1e-4f + (0.2f - 1e-4f) * ((float)i / 99.0f);
        float alpha = 1.0f - beta;
        float abprev = ab;
        ab *= alpha;
        float one_m_ab = 1.0f - ab;
        float post_var = beta * (1.0f - abprev) / one_m_ab;
        g_sr [i] = sqrtf(1.0f / ab);
        g_srm[i] = sqrtf(1.0f / ab - 1.0f);
        g_p1 [i] = beta * sqrtf(abprev) / one_m_ab;
        g_p2 [i] = (1.0f - abprev) * sqrtf(alpha) / one_m_ab;
        g_sig[i] = sqrtf(fmaxf(post_var, 1e-20f));
    }
}

// ---------------- per-step time-embedding vector precompute ----------------
__global__ void temb_kernel(const float* __restrict__ w_t1, const float* __restrict__ b_t1,
                            const float* __restrict__ w_t2, const float* __restrict__ b_t2,
                            const float* __restrict__ w1t) {
    int i = blockIdx.x;
    int t = threadIdx.x;
    __shared__ float emb[16];
    __shared__ float e1[256];
    __shared__ float temb[16];

    if (t < 8) {
        float freq = expf((float)t * (-logf(10000.0f) / 7.0f));
        float ang  = (float)i * freq;
        emb[t]     = sinf(ang);
        emb[t + 8] = cosf(ang);
    }
    __syncthreads();
    {
        float s = b_t1[t];
        #pragma unroll
        for (int j = 0; j < 16; j++) s += emb[j] * w_t1[j * 256 + t];
        e1[t] = mishf(s);
    }
    __syncthreads();
    if (t < 16) {
        float s = b_t2[t];
        for (int p = 0; p < 256; p++) s += e1[p] * w_t2[p * 16 + t];
        temb[t] = s;
    }
    __syncthreads();
    for (int n = t; n < H_SZ; n += 256) {
        float s = 0.0f;
        #pragma unroll
        for (int q = 0; q < 16; q++) s += temb[q] * w1t[q * H_SZ + n];
        g_tv[i * H_SZ + n] = s;
    }
}

__global__ void copy_x_kernel(const float* __restrict__ x_init) {
    int idx = blockIdx.x * blockDim.x + threadIdx.x;
    float v = x_init[idx];
    g_x[idx]  = v;
    g_xr[idx] = __uint_as_float(f2tf32(v));
}
__global__ void clip_out_kernel(float* __restrict__ out) {
    int idx = blockIdx.x * blockDim.x + threadIdx.x;
    out[idx] = fminf(fmaxf(g_x[idx], -1.0f), 1.0f);
}
__global__ void round_copy_kernel(const float* __restrict__ src, float* __restrict__ dst) {
    int idx = blockIdx.x * blockDim.x + threadIdx.x;
    dst[idx] = __uint_as_float(f2tf32(src[idx]));
}
__global__ void half_copy_kernel(const float* __restrict__ src, __half* __restrict__ dst) {
    int idx = blockIdx.x * blockDim.x + threadIdx.x;
    dst[idx] = __float2half(src[idx]);
}
// dst[N][K] = half(src[K][N])
__global__ void transpose_half_kernel(const float* __restrict__ src, __half* __restrict__ dst,
                                      int Kdim, int Ndim) {
    __shared__ float tile[32][33];
    int kb = blockIdx.y * 32, nb = blockIdx.x * 32;
    int tx = threadIdx.x, ty = threadIdx.y;  // 32 x 8
    #pragma unroll
    for (int j = 0; j < 32; j += 8)
        tile[ty + j][tx] = src[(size_t)(kb + ty + j) * Ndim + nb + tx];
    __syncthreads();
    #pragma unroll
    for (int j = 0; j < 32; j += 8)
        dst[(size_t)(nb + ty + j) * Kdim + kb + tx] = __float2half(tile[tx][ty + j]);
}

// ================= fp16 mma.sync GEMM: C = epi(A[M,K]h @ Bt[N,K]h^T) =================
// Tile 128x128, BK=64 (128B rows, XOR-8 swizzle), 3-stage cp.async, ldmatrix.x4.
// 8 warps, warptile 32x64, 2 CTAs/SM.  EPI 0: float out, +bias.  EPI 1: half out, mish.
#define HG_STG 32768            // per stage: A 128*64*2 + B 128*64*2 = 16KB+16KB
#define HG_SMEM (3 * HG_STG)    // 98304

__device__ __forceinline__ void hg_fill(uint32_t sAu, uint32_t sBu,
                                        const __half* Ag, const __half* Bg,
                                        int K, int kk, int tid) {
    int r = tid >> 1, cb = (tid & 1) * 4;
    #pragma unroll
    for (int i = 0; i < 4; i++) {
        int c = cb + i;
        uint32_t off = r * 128 + ((c ^ (r & 7)) << 4);
        cpa16(sAu + off, Ag + (size_t)r * K + kk + c * 8);
        cpa16(sBu + off, Bg + (size_t)r * K + kk + c * 8);
    }
}

template <int EPI>
__global__ __launch_bounds__(256, 2)
void hgemm(const __half* __restrict__ A, const __half* __restrict__ Bt,
           const float* __restrict__ bias, void* __restrict__ Cv,
           int K, int N) {
    extern __shared__ __align__(16) char smem_raw[];
    const uint32_t sbase = smem_u32(smem_raw);
    const int tid  = threadIdx.x;
    const int lane = tid & 31;
    const int warp = tid >> 5;
    const int warpM = (warp & 3) * 32;     // 0,32,64,96
    const int warpN = (warp >> 2) * 64;    // 0,64
    const int g  = lane >> 2;
    const int t4 = lane & 3;
    const int m0 = blockIdx.y * 128;
    const int n0 = blockIdx.x * 128;
    const __half* Ag = A  + (size_t)m0 * K;
    const __half* Bg = Bt + (size_t)n0 * K;
    const int nIter = K / 64;

    float acc[2][8][4];
    #pragma unroll
    for (int i = 0; i < 2; i++)
        #pragma unroll
        for (int j = 0; j < 8; j++)
            #pragma unroll
            for (int q = 0; q < 4; q++) acc[i][j][q] = 0.0f;

    hg_fill(sbase, sbase + 16384, Ag, Bg, K, 0, tid);
    CP_COMMIT();
    hg_fill(sbase + HG_STG, sbase + HG_STG + 16384, Ag, Bg, K, 64, tid);
    CP_COMMIT();

    const int lo7  = lane & 7;
    const int aRow = lane & 15;
    const int aHi  = lane >> 4;
    const int bRow = (lane & 7) + ((lane >> 4) << 3);
    const int bHi  = (lane >> 3) & 1;

    for (int it = 0; it < nIter; ++it) {
        cp_wait<1>();
        __syncthreads();
        int nxt = it + 2;
        if (nxt < nIter) {
            uint32_t sf = sbase + (nxt % 3) * HG_STG;
            hg_fill(sf, sf + 16384, Ag, Bg, K, nxt * 64, tid);
        }
        CP_COMMIT();

        const uint32_t sAu = sbase + (it % 3) * HG_STG;
        const uint32_t sBu = sAu + 16384;

        #pragma unroll
        for (int ks = 0; ks < 4; ks++) {
            uint32_t a[2][4], b[4][4];
            #pragma unroll
            for (int mi = 0; mi < 2; mi++) {
                int row = warpM + mi * 16 + aRow;
                ldm4(a[mi], sAu + row * 128 + (((2 * ks + aHi) ^ lo7) << 4));
            }
            #pragma unroll
            for (int p = 0; p < 4; p++) {
                int row = warpN + p * 16 + bRow;
                ldm4(b[p], sBu + row * 128 + (((2 * ks + bHi) ^ lo7) << 4));
            }
            #pragma unroll
            for (int mi = 0; mi < 2; mi++)
                #pragma unroll
                for (int p = 0; p < 4; p++) {
                    mma16816(acc[mi][2 * p],     a[mi], b[p][0], b[p][1]);
                    mma16816(acc[mi][2 * p + 1], a[mi], b[p][2], b[p][3]);
                }
        }
    }

    // epilogue
    float2 bv[8];
    #pragma unroll
    for (int ni = 0; ni < 8; ni++) {
        int col = n0 + warpN + ni * 8 + t4 * 2;
        bv[ni] = make_float2(bias[col], bias[col + 1]);
    }
    #pragma unroll
    for (int mi = 0; mi < 2; mi++) {
        int row0 = m0 + warpM + mi * 16 + g;
        int row1 = row0 + 8;
        #pragma unroll
        for (int ni = 0; ni < 8; ni++) {
            int col = n0 + warpN + ni * 8 + t4 * 2;
            float s0 = acc[mi][ni][0] + bv[ni].x;
            float s1 = acc[mi][ni][1] + bv[ni].y;
            float s2 = acc[mi][ni][2] + bv[ni].x;
            float s3 = acc[mi][ni][3] + bv[ni].y;
            if (EPI == 1) {
                s0 = mishf(s0); s1 = mishf(s1); s2 = mishf(s2); s3 = mishf(s3);
                __half* C = (__half*)Cv;
                *reinterpret_cast<__half2*>(C + (size_t)row0 * N + col) = __floats2half2_rn(s0, s1);
                *reinterpret_cast<__half2*>(C + (size_t)row1 * N + col) = __floats2half2_rn(s2, s3);
            } else {
                float* C = (float*)Cv;
                *reinterpret_cast<float2*>(C + (size_t)row0 * N + col) = make_float2(s0, s1);
                *reinterpret_cast<float2*>(C + (size_t)row1 * N + col) = make_float2(s2, s3);
            }
        }
    }
}

// ---------------- layer-1 tf32 mma.sync GEMM (K=32), 128x128, half out ----------------
#define STAGES 3
#define BKF 32
extern __shared__ float smem_f[];

__global__ __launch_bounds__(256, 2)
void l1gemm(const float* __restrict__ A, const float* __restrict__ Bm,
            const float* __restrict__ bias, const float* __restrict__ add,
            __half* __restrict__ C, int M, int N, int K) {
    const int tid  = threadIdx.x;
    const int lane = tid & 31;
    const int warp = tid >> 5;
    const int warpM = (warp >> 2) * 64;
    const int warpN = (warp & 3) * 32;
    const int groupID = lane >> 2;
    const int tid4    = lane & 3;

    const int m0 = blockIdx.y * 128;
    const int n0 = blockIdx.x * 128;

    const int am   = tid >> 1;
    const int ak4b = (tid & 1) * 4;
    const int bk   = tid >> 3;
    const int bn4b = (tid & 7) * 4;

    const float* Abase = A + (size_t)(m0 + am) * K;
    const float* Bbase = Bm + (size_t)bk * N + n0;

    const int nIter = K / BKF;

    float acc[4][4][4];
    #pragma unroll
    for (int i = 0; i < 4; i++)
        #pragma unroll
        for (int j = 0; j < 4; j++)
            #pragma unroll
            for (int q = 0; q < 4; q++) acc[i][j][q] = 0.0f;

    int aOff[4], bOff[4];
    #pragma unroll
    for (int i = 0; i < 4; i++) {
        int k4 = ak4b + i;
        aOff[i] = am * 32 + ((k4 ^ (am & 7)) << 2);
        int n4 = bn4b + i;
        int gsw = (n4 & 0x18) | ((2 * bk + n4) & 7);
        bOff[i] = bk * 128 + (gsw << 2);
    }

    #pragma unroll
    for (int s = 0; s < STAGES - 1; s++) {
        if (s < nIter) {
            float* sA = smem_f + s * 4096;
            float* sB = smem_f + STAGES * 4096 + s * 4096;
            int kk = s * BKF;
            #pragma unroll
            for (int i = 0; i < 4; i++) {
                cpa16(smem_u32(sA + aOff[i]), Abase + kk + (ak4b + i) * 4);
                cpa16(smem_u32(sB + bOff[i]), Bbase + (size_t)kk * N + (bn4b + i) * 4);
            }
        }
        CP_COMMIT();
    }

    int bFragOff[4];
    #pragma unroll
    for (int ni = 0; ni < 4; ni++) {
        int n4 = (warpN >> 2) + 2 * ni + (groupID >> 2);
        int gsw = (n4 & 0x18) | ((2 * tid4 + n4) & 7);
        bFragOff[ni] = (gsw << 2) + (groupID & 3);
    }
    int aRowOff[4];
    #pragma unroll
    for (int mi = 0; mi < 4; mi++)
        aRowOff[mi] = (warpM + mi * 16 + groupID) * 32 + tid4;

    for (int it = 0; it < nIter; ++it) {
        cp_wait<STAGES - 2>();
        __syncthreads();

        int nxt = it + STAGES - 1;
        if (nxt < nIter) {
            int buf = nxt % STAGES;
            float* sA = smem_f + buf * 4096;
            float* sB = smem_f + STAGES * 4096 + buf * 4096;
            int kk = nxt * BKF;
            #pragma unroll
            for (int i = 0; i < 4; i++) {
                cpa16(smem_u32(sA + aOff[i]), Abase + kk + (ak4b + i) * 4);
                cpa16(smem_u32(sB + bOff[i]), Bbase + (size_t)kk * N + (bn4b + i) * 4);
            }
        }
        CP_COMMIT();

        const float* sA = smem_f + (it % STAGES) * 4096;
        const float* sB = smem_f + STAGES * 4096 + (it % STAGES) * 4096;

        #pragma unroll
        for (int ks = 0; ks < 4; ks++) {
            const int swz0 = ((2 * ks)     ^ groupID) << 2;
            const int swz1 = ((2 * ks + 1) ^ groupID) << 2;
            uint32_t af[4][4], bfr[4][2];
            #pragma unroll
            for (int mi = 0; mi < 4; mi++) {
                af[mi][0] = __float_as_uint(sA[aRowOff[mi]       + swz0]);
                af[mi][1] = __float_as_uint(sA[aRowOff[mi] + 256 + swz0]);
                af[mi][2] = __float_as_uint(sA[aRowOff[mi]       + swz1]);
                af[mi][3] = __float_as_uint(sA[aRowOff[mi] + 256 + swz1]);
            }
            const int kRow0 = (8 * ks + tid4) * 128;
            const int kRow1 = kRow0 + 4 * 128;
            #pragma unroll
            for (int ni = 0; ni < 4; ni++) {
                bfr[ni][0] = __float_as_uint(sB[kRow0 + bFragOff[ni]]);
                bfr[ni][1] = __float_as_uint(sB[kRow1 + bFragOff[ni]]);
            }
            #pragma unroll
            for (int mi = 0; mi < 4; mi++)
                #pragma unroll
                for (int ni = 0; ni < 4; ni++) {
                    asm volatile(
                        "mma.sync.aligned.m16n8k8.row.col.f32.tf32.tf32.f32 "
                        "{%0,%1,%2,%3}, {%4,%5,%6,%7}, {%8,%9}, {%0,%1,%2,%3};"
                        : "+f"(acc[mi][ni][0]), "+f"(acc[mi][ni][1]),
                          "+f"(acc[mi][ni][2]), "+f"(acc[mi][ni][3])
                        : "r"(af[mi][0]), "r"(af[mi][1]), "r"(af[mi][2]), "r"(af[mi][3]),
                          "r"(bfr[ni][0]), "r"(bfr[ni][1]));
                }
        }
    }

    #pragma unroll
    for (int mi = 0; mi < 4; mi++) {
        int row0 = m0 + warpM + mi * 16 + groupID;
        int row1 = row0 + 8;
        #pragma unroll
        for (int ni = 0; ni < 4; ni++) {
            int col = n0 + warpN + ni * 8 + tid4 * 2;
            float b0v = bias[col], b1v = bias[col + 1];
            float s0 = acc[mi][ni][0] + b0v + add[(size_t)row0 * N + col];
            float s1 = acc[mi][ni][1] + b1v + add[(size_t)row0 * N + col + 1];
            float s2 = acc[mi][ni][2] + b0v + add[(size_t)row1 * N + col];
            float s3 = acc[mi][ni][3] + b1v + add[(size_t)row1 * N + col + 1];
            s0 = mishf(s0); s1 = mishf(s1); s2 = mishf(s2); s3 = mishf(s3);
            *reinterpret_cast<__half2*>(C + (size_t)row0 * N + col) = __floats2half2_rn(s0, s1);
            *reinterpret_cast<__half2*>(C + (size_t)row1 * N + col) = __floats2half2_rn(s2, s3);
        }
    }
}

// ---------------- fused final-layer GEMM (N=32) + diffusion update ----------------
__global__ __launch_bounds__(256)
void update_kernel(const float* __restrict__ wf, const float* __restrict__ bf,
                   const float* __restrict__ noise, int step) {
    __shared__ float As[32][32];
    __shared__ float Bs[32][32];
    int tid = threadIdx.x;
    int bm  = blockIdx.x * 32;
    int tx = tid & 31, ty = tid >> 5;
    int lr = tid >> 3;
    int lc = (tid & 7) * 4;

    float acc[4] = {0.f, 0.f, 0.f, 0.f};
    for (int kk = 0; kk < H_SZ; kk += 32) {
        {
            const __half2* hp = reinterpret_cast<const __half2*>(
                &g_h1h[(size_t)(bm + lr) * H_SZ + kk + lc]);
            float2 f0 = __half22float2(hp[0]);
            float2 f1 = __half22float2(hp[1]);
            As[lr][lc]     = f0.x; As[lr][lc + 1] = f0.y;
            As[lr][lc + 2] = f1.x; As[lr][lc + 3] = f1.y;
        }
        *reinterpret_cast<float4*>(&Bs[lr][lc]) =
            *reinterpret_cast<const float4*>(wf + (size_t)(kk + lr) * 32 + lc);
        __syncthreads();
        #pragma unroll
        for (int k = 0; k < 32; k++) {
            float b = Bs[k][tx];
            #pragma unroll
            for (int r = 0; r < 4; r++)
                acc[r] = fmaf(As[ty * 4 + r][k], b, acc[r]);
        }
        __syncthreads();
    }

    float sr  = g_sr[step], srm = g_srm[step];
    float p1  = g_p1[step], p2  = g_p2[step];
    float sig = (step != 0) ? g_sig[step] : 0.0f;
    const float* z = noise + (size_t)(T_STEPS - 1 - step) * B_SZ * A_SZ;

    #pragma unroll
    for (int r = 0; r < 4; r++) {
        int m = bm + ty * 4 + r;
        float eps = acc[r] + bf[tx];
        float xo  = g_x[(size_t)m * A_SZ + tx];
        float xr  = fminf(fmaxf(sr * xo - srm * eps, -1.0f), 1.0f);
        float xn  = p1 * xr + p2 * xo + sig * z[(size_t)m * A_SZ + tx];
        g_x [(size_t)m * A_SZ + tx] = xn;
        g_xr[(size_t)m * A_SZ + tx] = __uint_as_float(f2tf32(xn));
    }
}

// ---------------- launch ----------------
extern "C" void kernel_launch(void* const* d_in, const int* in_sizes, int n_in,
                              void* d_out, int out_size) {
    const float* state  = (const float*)d_in[0];
    const float* w_t1   = (const float*)d_in[1];
    const float* b_t1   = (const float*)d_in[2];
    const float* w_t2   = (const float*)d_in[3];
    const float* b_t2   = (const float*)d_in[4];
    const float* w1     = (const float*)d_in[5];
    const float* b1     = (const float*)d_in[6];
    const float* w2     = (const float*)d_in[7];
    const float* b2     = (const float*)d_in[8];
    const float* w3     = (const float*)d_in[9];
    const float* b3     = (const float*)d_in[10];
    const float* wf     = (const float*)d_in[11];
    const float* bf     = (const float*)d_in[12];
    const float* x_init = (const float*)d_in[13];
    const float* noise  = (const float*)d_in[14];

    float *p_xr, *p_cs, *p_tv, *p_w1x_r;
    __half *p_h1h, *p_h2h, *p_state_h, *p_w1st_h, *p_w2t_h, *p_w3t_h;
    cudaGetSymbolAddress((void**)&p_xr,     g_xr);
    cudaGetSymbolAddress((void**)&p_cs,     g_cs);
    cudaGetSymbolAddress((void**)&p_tv,     g_tv);
    cudaGetSymbolAddress((void**)&p_w1x_r,  g_w1x_r);
    cudaGetSymbolAddress((void**)&p_h1h,    g_h1h);
    cudaGetSymbolAddress((void**)&p_h2h,    g_h2h);
    cudaGetSymbolAddress((void**)&p_state_h, g_state_h);
    cudaGetSymbolAddress((void**)&p_w1st_h, g_w1st_h);
    cudaGetSymbolAddress((void**)&p_w2t_h,  g_w2t_h);
    cudaGetSymbolAddress((void**)&p_w3t_h,  g_w3t_h);

    const int L1_SMEM = STAGES * 2 * 4096 * sizeof(float);  // 98304
    cudaFuncSetAttribute(l1gemm, cudaFuncAttributeMaxDynamicSharedMemorySize, L1_SMEM);
    cudaFuncSetAttribute(hgemm<0>, cudaFuncAttributeMaxDynamicSharedMemorySize, HG_SMEM);
    cudaFuncSetAttribute(hgemm<1>, cudaFuncAttributeMaxDynamicSharedMemorySize, HG_SMEM);

    dim3 gh(H_SZ / 128, B_SZ / 128);    // (8, 32) = 256 CTAs, 2/SM
    dim3 gl1(H_SZ / 128, B_SZ / 128);   // (8, 32)
    dim3 blkT(32, 8);

    // Launch order chosen so ncu's "-s 5 -c 1" window (6th launch) lands on hgemm<0>.
    sched_kernel<<<1, 32>>>();                                         // 1
    copy_x_kernel<<<(B_SZ * A_SZ) / 256, 256>>>(x_init);               // 2
    round_copy_kernel<<<(A_SZ * H_SZ) / 256, 256>>>(w1, p_w1x_r);      // 3
    half_copy_kernel<<<(B_SZ * S_SZ) / 256, 256>>>(state, p_state_h);  // 4
    transpose_half_kernel<<<dim3(H_SZ / 32, S_SZ / 32), blkT>>>(w1 + 48 * H_SZ, p_w1st_h, S_SZ, H_SZ); // 5
    // C_state = state @ W1_state + b1  (once, fp32 out)  -- PROFILED LAUNCH
    hgemm<0><<<gh, 256, HG_SMEM>>>(p_state_h, p_w1st_h, b1, p_cs, S_SZ, H_SZ);  // 6

    temb_kernel<<<T_STEPS, 256>>>(w_t1, b_t1, w_t2, b_t2, w1 + 32 * H_SZ);
    transpose_half_kernel<<<dim3(H_SZ / 32, H_SZ / 32), blkT>>>(w2, p_w2t_h, H_SZ, H_SZ);
    transpose_half_kernel<<<dim3(H_SZ / 32, H_SZ / 32), blkT>>>(w3, p_w3t_h, H_SZ, H_SZ);

    for (int i = T_STEPS - 1; i >= 0; --i) {
        // h1 = mish(x @ W1x + cs + tv[i])   (tf32 path, K=32, half out)
        l1gemm<<<gl1, 256, L1_SMEM>>>(p_xr, p_w1x_r, p_tv + i * H_SZ, p_cs, p_h1h, B_SZ, H_SZ, A_SZ);
        // h2 = mish(h1 @ W2 + b2)   (fp16 mma)
        hgemm<1><<<gh, 256, HG_SMEM>>>(p_h1h, p_w2t_h, b2, p_h2h, H_SZ, H_SZ);
        // h3 = mish(h2 @ W3 + b3)   (fp16 mma)
        hgemm<1><<<gh, 256, HG_SMEM>>>(p_h2h, p_w3t_h, b3, p_h1h, H_SZ, H_SZ);
        // eps + diffusion update (fused)
        update_kernel<<<B_SZ / 32, 256>>>(wf, bf, noise, i);
    }
    clip_out_kernel<<<(B_SZ * A_SZ) / 256, 256>>>((float*)d_out);
}